// round 12
// baseline (speedup 1.0000x reference)
#include <cuda_runtime.h>
#include <cuda_bf16.h>
#include <stdint.h>
#include <math.h>

// Problem constants
#define BATCH 4
#define NQ 2048
#define NK 2048
#define DM 1024

// ---------------------------------------------------------------------------
// Scratch (device globals)
// ---------------------------------------------------------------------------
__device__ float g_Kp[BATCH * NK * DM];
__device__ float g_negent[BATCH * NK];
__device__ float g_inv[BATCH * NQ];
__device__ float g_attn[BATCH * NQ * NK];   // fallback if harness wants only `out`

__device__ __nv_bfloat16 g_Qh[BATCH * NQ * DM],  g_Ql[BATCH * NQ * DM];
__device__ __nv_bfloat16 g_Kh[BATCH * NK * DM],  g_Kl[BATCH * NK * DM];
__device__ __nv_bfloat16 g_Vh[BATCH * NK * DM],  g_Vl[BATCH * NK * DM];
__device__ __nv_bfloat16 g_Wqh[DM * DM], g_Wql[DM * DM];
__device__ __nv_bfloat16 g_Wkh[DM * DM], g_Wkl[DM * DM];
__device__ __nv_bfloat16 g_Wvh[DM * DM], g_Wvl[DM * DM];
__device__ __nv_bfloat16 g_Qph[BATCH * NQ * DM], g_Qpl[BATCH * NQ * DM];
__device__ __nv_bfloat16 g_pKh[BATCH * NK * DM], g_pKl[BATCH * NK * DM];
__device__ __nv_bfloat16 g_VpTh[BATCH * DM * NK], g_VpTl[BATCH * DM * NK];
__device__ __nv_bfloat16 g_Ath[BATCH * NQ * NK], g_Atl[BATCH * NQ * NK];  // unnormalized exp splits

// ---------------------------------------------------------------------------
// Common MMA helpers
// ---------------------------------------------------------------------------
#define KC 32
#define SROW 40
#define TILEE (128 * SROW)
#define GEMM_SMEM (2 * 4 * TILEE * 2)            // 81920 bytes

__device__ __forceinline__ void ldsm_x4(uint32_t* r, uint32_t addr) {
    asm volatile("ldmatrix.sync.aligned.m8n8.x4.shared.b16 {%0,%1,%2,%3}, [%4];"
                 : "=r"(r[0]), "=r"(r[1]), "=r"(r[2]), "=r"(r[3]) : "r"(addr));
}
__device__ __forceinline__ void mma_bf16(float* c, const uint32_t* a, uint32_t b0, uint32_t b1) {
    asm volatile(
        "mma.sync.aligned.m16n8k16.row.col.f32.bf16.bf16.f32 "
        "{%0,%1,%2,%3}, {%4,%5,%6,%7}, {%8,%9}, {%0,%1,%2,%3};"
        : "+f"(c[0]), "+f"(c[1]), "+f"(c[2]), "+f"(c[3])
        : "r"(a[0]), "r"(a[1]), "r"(a[2]), "r"(a[3]), "r"(b0), "r"(b1));
}
__device__ __forceinline__ void split1(float v, __nv_bfloat16& h, __nv_bfloat16& l) {
    h = __float2bfloat16(v);
    l = __float2bfloat16(v - __bfloat162float(h));
}

// ---------------------------------------------------------------------------
// Mainloop body: acc = Ah*Bh + Al*Bh + Ah*Bl over K for CTA tile (m0,n0)
// ---------------------------------------------------------------------------
struct GemmCore {
    const __nv_bfloat16 *Ah, *Al, *Bh, *Bl;
    int m0, n0, K;

    __device__ __forceinline__ void run(__nv_bfloat16* smem, float acc[4][4][4],
                                        int tid, int lane, int wid) const
    {
        const int m_warp = (wid >> 2) * 64;
        const int n_warp = (wid & 3) * 32;
        const int nt = K / KC;
        const int lrow = tid >> 2;
        const int lc   = (tid & 3) * 8;

        auto issue = [&](int c, int stage) {
            const int k0 = c * KC;
            __nv_bfloat16* sbase = smem + stage * 4 * TILEE;
            const __nv_bfloat16* srcs[4] = {Ah, Al, Bh, Bl};
            #pragma unroll
            for (int v = 0; v < 4; v++) {
                const __nv_bfloat16* src = srcs[v];
                const int g0 = (v < 2) ? m0 : n0;
                __nv_bfloat16* dstv = sbase + v * TILEE;
                #pragma unroll
                for (int i = 0; i < 2; i++) {
                    const int row = lrow + i * 64;
                    const void* g = src + (long long)(g0 + row) * K + k0 + lc;
                    uint32_t d = (uint32_t)__cvta_generic_to_shared(dstv + row * SROW + lc);
                    asm volatile("cp.async.cg.shared.global [%0], [%1], 16;" :: "r"(d), "l"(g));
                }
            }
            asm volatile("cp.async.commit_group;");
        };

        const int ar  = lane & 15;
        const int ac8 = (lane >> 4) & 1;
        const int br  = (lane & 7) + ((lane & 16) ? 8 : 0);
        const int bc8 = (lane >> 3) & 1;

        issue(0, 0);
        if (nt > 1) issue(1, 1);

        for (int t = 0; t < nt; t++) {
            if (t + 1 < nt) { asm volatile("cp.async.wait_group 1;"); }
            else            { asm volatile("cp.async.wait_group 0;"); }
            __syncthreads();

            const int stage = t & 1;
            const uint32_t sb = (uint32_t)__cvta_generic_to_shared(smem + stage * 4 * TILEE);
            const uint32_t ab_h = sb;
            const uint32_t ab_l = sb + TILEE * 2;
            const uint32_t bb_h = sb + 2 * TILEE * 2;
            const uint32_t bb_l = sb + 3 * TILEE * 2;

            #pragma unroll
            for (int k16 = 0; k16 < 2; k16++) {
                uint32_t ah[4][4], bh[2][4];
                #pragma unroll
                for (int tm = 0; tm < 4; tm++)
                    ldsm_x4(ah[tm], ab_h + ((m_warp + tm * 16 + ar) * SROW + k16 * 16 + ac8 * 8) * 2);
                #pragma unroll
                for (int p = 0; p < 2; p++)
                    ldsm_x4(bh[p], bb_h + ((n_warp + p * 16 + br) * SROW + k16 * 16 + bc8 * 8) * 2);
                #pragma unroll
                for (int tm = 0; tm < 4; tm++)
                    #pragma unroll
                    for (int tn = 0; tn < 4; tn++)
                        mma_bf16(acc[tm][tn], ah[tm],
                                 bh[tn >> 1][(tn & 1) * 2], bh[tn >> 1][(tn & 1) * 2 + 1]);
                {
                    uint32_t al[4][4];
                    #pragma unroll
                    for (int tm = 0; tm < 4; tm++)
                        ldsm_x4(al[tm], ab_l + ((m_warp + tm * 16 + ar) * SROW + k16 * 16 + ac8 * 8) * 2);
                    #pragma unroll
                    for (int tm = 0; tm < 4; tm++)
                        #pragma unroll
                        for (int tn = 0; tn < 4; tn++)
                            mma_bf16(acc[tm][tn], al[tm],
                                     bh[tn >> 1][(tn & 1) * 2], bh[tn >> 1][(tn & 1) * 2 + 1]);
                }
                {
                    uint32_t bl[2][4];
                    #pragma unroll
                    for (int p = 0; p < 2; p++)
                        ldsm_x4(bl[p], bb_l + ((n_warp + p * 16 + br) * SROW + k16 * 16 + bc8 * 8) * 2);
                    #pragma unroll
                    for (int tm = 0; tm < 4; tm++)
                        #pragma unroll
                        for (int tn = 0; tn < 4; tn++)
                            mma_bf16(acc[tm][tn], ah[tm],
                                     bl[tn >> 1][(tn & 1) * 2], bl[tn >> 1][(tn & 1) * 2 + 1]);
                }
            }
            __syncthreads();
            if (t + 2 < nt) issue(t + 2, stage);
        }
    }
};

// ---------------------------------------------------------------------------
// Merged projection GEMM: grid.z selects {Q, K, V}. P = X @ W^T + b.
//   z=0 (Q): write Qp split bf16.
//   z=1 (K): write Kp fp32 (consumed by softmax_ent).
//   z=2 (V): write VpT split bf16 via in-smem transpose (no fp32 Vp at all).
// ---------------------------------------------------------------------------
#define TPAD 132   // fp32 transpose-stage row pitch (16B-aligned rows)

__global__ void __launch_bounds__(256, 2)
proj_gemm(const __nv_bfloat16* __restrict__ Qh, const __nv_bfloat16* __restrict__ Ql,
          const __nv_bfloat16* __restrict__ Kh, const __nv_bfloat16* __restrict__ Kl,
          const __nv_bfloat16* __restrict__ Vh, const __nv_bfloat16* __restrict__ Vl,
          const __nv_bfloat16* __restrict__ Wqh, const __nv_bfloat16* __restrict__ Wql,
          const __nv_bfloat16* __restrict__ Wkh, const __nv_bfloat16* __restrict__ Wkl,
          const __nv_bfloat16* __restrict__ Wvh, const __nv_bfloat16* __restrict__ Wvl,
          const float* __restrict__ bq, const float* __restrict__ bk,
          const float* __restrict__ bv,
          __nv_bfloat16* __restrict__ Qph, __nv_bfloat16* __restrict__ Qpl,
          float* __restrict__ Kp,
          __nv_bfloat16* __restrict__ VpTh, __nv_bfloat16* __restrict__ VpTl)
{
    extern __shared__ __align__(16) __nv_bfloat16 smem[];
    const int tid = threadIdx.x, lane = tid & 31, wid = tid >> 5;
    const int z = blockIdx.z;

    GemmCore core;
    const float* bias;
    if (z == 0)      { core.Ah = Qh; core.Al = Ql; core.Bh = Wqh; core.Bl = Wql; bias = bq; }
    else if (z == 1) { core.Ah = Kh; core.Al = Kl; core.Bh = Wkh; core.Bl = Wkl; bias = bk; }
    else             { core.Ah = Vh; core.Al = Vl; core.Bh = Wvh; core.Bl = Wvl; bias = bv; }
    core.m0 = blockIdx.y * 128; core.n0 = blockIdx.x * 128; core.K = DM;

    float acc[4][4][4];
    #pragma unroll
    for (int i = 0; i < 4; i++)
        #pragma unroll
        for (int j = 0; j < 4; j++)
            #pragma unroll
            for (int r = 0; r < 4; r++) acc[i][j][r] = 0.f;

    core.run(smem, acc, tid, lane, wid);

    const int m_warp = (wid >> 2) * 64;
    const int n_warp = (wid & 3) * 32;
    const int N = DM;

    if (z == 2) {
        // Stage tile TRANSPOSED in smem (fp32), then write VpT splits coalesced.
        float* tileT = (float*)smem;
        __syncthreads();  // done with mainloop smem
        #pragma unroll
        for (int tm = 0; tm < 4; tm++) {
            #pragma unroll
            for (int tn = 0; tn < 4; tn++) {
                const int lr = m_warp + tm * 16 + (lane >> 2);
                const int lcol = n_warp + tn * 8 + (lane & 3) * 2;
                const float2 bb = *(const float2*)&bias[core.n0 + lcol];
                tileT[(lcol)     * TPAD + lr]     = acc[tm][tn][0] + bb.x;
                tileT[(lcol + 1) * TPAD + lr]     = acc[tm][tn][1] + bb.y;
                tileT[(lcol)     * TPAD + lr + 8] = acc[tm][tn][2] + bb.x;
                tileT[(lcol + 1) * TPAD + lr + 8] = acc[tm][tn][3] + bb.y;
            }
        }
        __syncthreads();
        const int b   = core.m0 >> 11;            // batch (2048 tokens each)
        const int tk0 = core.m0 & 2047;           // token base within batch
        __nv_bfloat16* Hh = VpTh + (long long)b * DM * NK;
        __nv_bfloat16* Hl = VpTl + (long long)b * DM * NK;
        #pragma unroll
        for (int i = 0; i < 16; i++) {
            const int c = wid * 16 + i;           // 0..127 headdim-within-tile
            const float4 v = *(const float4*)&tileT[c * TPAD + lane * 4];
            __nv_bfloat16 h0, l0, h1, l1, h2, l2, h3, l3;
            split1(v.x, h0, l0); split1(v.y, h1, l1);
            split1(v.z, h2, l2); split1(v.w, h3, l3);
            const long long o = (long long)(core.n0 + c) * NK + tk0 + lane * 4;
            *(__nv_bfloat162*)&Hh[o]     = __nv_bfloat162(h0, h1);
            *(__nv_bfloat162*)&Hh[o + 2] = __nv_bfloat162(h2, h3);
            *(__nv_bfloat162*)&Hl[o]     = __nv_bfloat162(l0, l1);
            *(__nv_bfloat162*)&Hl[o + 2] = __nv_bfloat162(l2, l3);
        }
        return;
    }

    #pragma unroll
    for (int tm = 0; tm < 4; tm++) {
        #pragma unroll
        for (int tn = 0; tn < 4; tn++) {
            const int row = core.m0 + m_warp + tm * 16 + (lane >> 2);
            const int col = core.n0 + n_warp + tn * 8 + (lane & 3) * 2;
            const float2 bb = *(const float2*)&bias[col];
            float2 v0 = make_float2(acc[tm][tn][0] + bb.x, acc[tm][tn][1] + bb.y);
            float2 v1 = make_float2(acc[tm][tn][2] + bb.x, acc[tm][tn][3] + bb.y);
            if (z == 0) {
                __nv_bfloat16 h0, l0, h1, l1;
                split1(v0.x, h0, l0); split1(v0.y, h1, l1);
                *(__nv_bfloat162*)&Qph[(long long)row * N + col] = __nv_bfloat162(h0, h1);
                *(__nv_bfloat162*)&Qpl[(long long)row * N + col] = __nv_bfloat162(l0, l1);
                split1(v1.x, h0, l0); split1(v1.y, h1, l1);
                *(__nv_bfloat162*)&Qph[(long long)(row + 8) * N + col] = __nv_bfloat162(h0, h1);
                *(__nv_bfloat162*)&Qpl[(long long)(row + 8) * N + col] = __nv_bfloat162(l0, l1);
            } else {
                *(float2*)&Kp[(long long)row * N + col] = v0;
                *(float2*)&Kp[(long long)(row + 8) * N + col] = v1;
            }
        }
    }
}

// ---------------------------------------------------------------------------
// Scores GEMM (batched via z): E = exp(Qp.pK - negent_j), written as split bf16
// (unnormalized). No max subtraction needed: |scores| <~ 13, exp is fp32-safe.
// ---------------------------------------------------------------------------
__global__ void __launch_bounds__(256, 2)
scores_gemm(const __nv_bfloat16* __restrict__ Qph, const __nv_bfloat16* __restrict__ Qpl,
            const __nv_bfloat16* __restrict__ pKh, const __nv_bfloat16* __restrict__ pKl,
            const float* __restrict__ negent,
            __nv_bfloat16* __restrict__ Ath, __nv_bfloat16* __restrict__ Atl)
{
    extern __shared__ __align__(16) __nv_bfloat16 smem[];
    const int tid = threadIdx.x, lane = tid & 31, wid = tid >> 5;
    const long long b = blockIdx.z;

    GemmCore core;
    core.Ah = Qph + b * NQ * DM; core.Al = Qpl + b * NQ * DM;
    core.Bh = pKh + b * NK * DM; core.Bl = pKl + b * NK * DM;
    core.m0 = blockIdx.y * 128; core.n0 = blockIdx.x * 128; core.K = DM;
    const float* ng = negent + b * NK;
    __nv_bfloat16* Hh = Ath + b * (long long)NQ * NK;
    __nv_bfloat16* Hl = Atl + b * (long long)NQ * NK;

    float acc[4][4][4];
    #pragma unroll
    for (int i = 0; i < 4; i++)
        #pragma unroll
        for (int j = 0; j < 4; j++)
            #pragma unroll
            for (int r = 0; r < 4; r++) acc[i][j][r] = 0.f;

    core.run(smem, acc, tid, lane, wid);

    const int m_warp = (wid >> 2) * 64;
    const int n_warp = (wid & 3) * 32;
    #pragma unroll
    for (int tm = 0; tm < 4; tm++) {
        #pragma unroll
        for (int tn = 0; tn < 4; tn++) {
            const int row = core.m0 + m_warp + tm * 16 + (lane >> 2);
            const int col = core.n0 + n_warp + tn * 8 + (lane & 3) * 2;
            const float2 nn = *(const float2*)&ng[col];
            const float e00 = expf(acc[tm][tn][0] - nn.x);
            const float e01 = expf(acc[tm][tn][1] - nn.y);
            const float e10 = expf(acc[tm][tn][2] - nn.x);
            const float e11 = expf(acc[tm][tn][3] - nn.y);
            __nv_bfloat16 h0, l0, h1, l1;
            split1(e00, h0, l0); split1(e01, h1, l1);
            *(__nv_bfloat162*)&Hh[(long long)row * NK + col] = __nv_bfloat162(h0, h1);
            *(__nv_bfloat162*)&Hl[(long long)row * NK + col] = __nv_bfloat162(l0, l1);
            split1(e10, h0, l0); split1(e11, h1, l1);
            *(__nv_bfloat162*)&Hh[(long long)(row + 8) * NK + col] = __nv_bfloat162(h0, h1);
            *(__nv_bfloat162*)&Hl[(long long)(row + 8) * NK + col] = __nv_bfloat162(l0, l1);
        }
    }
}

// ---------------------------------------------------------------------------
// Out GEMM (batched via z): out = (E @ VpT^T) * inv[row]
// ---------------------------------------------------------------------------
__global__ void __launch_bounds__(256, 2)
out_gemm(const __nv_bfloat16* __restrict__ Ath, const __nv_bfloat16* __restrict__ Atl,
         const __nv_bfloat16* __restrict__ VpTh, const __nv_bfloat16* __restrict__ VpTl,
         const float* __restrict__ inv, float* __restrict__ out)
{
    extern __shared__ __align__(16) __nv_bfloat16 smem[];
    const int tid = threadIdx.x, lane = tid & 31, wid = tid >> 5;
    const long long b = blockIdx.z;

    GemmCore core;
    core.Ah = Ath + b * (long long)NQ * NK; core.Al = Atl + b * (long long)NQ * NK;
    core.Bh = VpTh + b * (long long)DM * NK; core.Bl = VpTl + b * (long long)DM * NK;
    core.m0 = blockIdx.y * 128; core.n0 = blockIdx.x * 128; core.K = NK;
    const float* iv = inv + b * NQ;
    float* C = out + b * (long long)NQ * DM;

    float acc[4][4][4];
    #pragma unroll
    for (int i = 0; i < 4; i++)
        #pragma unroll
        for (int j = 0; j < 4; j++)
            #pragma unroll
            for (int r = 0; r < 4; r++) acc[i][j][r] = 0.f;

    core.run(smem, acc, tid, lane, wid);

    const int m_warp = (wid >> 2) * 64;
    const int n_warp = (wid & 3) * 32;
    #pragma unroll
    for (int tm = 0; tm < 4; tm++) {
        #pragma unroll
        for (int tn = 0; tn < 4; tn++) {
            const int row = core.m0 + m_warp + tm * 16 + (lane >> 2);
            const int col = core.n0 + n_warp + tn * 8 + (lane & 3) * 2;
            const float i0 = iv[row], i8 = iv[row + 8];
            float2 v0 = make_float2(acc[tm][tn][0] * i0, acc[tm][tn][1] * i0);
            float2 v1 = make_float2(acc[tm][tn][2] * i8, acc[tm][tn][3] * i8);
            *(float2*)&C[(long long)row * DM + col] = v0;
            *(float2*)&C[(long long)(row + 8) * DM + col] = v1;
        }
    }
}

// ---------------------------------------------------------------------------
// Merged input splits: grid.z selects {Q, K, V, Wq, Wk, Wv}
// ---------------------------------------------------------------------------
__global__ void __launch_bounds__(256)
split_all_kernel(const float* __restrict__ Q, const float* __restrict__ K,
                 const float* __restrict__ V, const float* __restrict__ Wq,
                 const float* __restrict__ Wk, const float* __restrict__ Wv,
                 __nv_bfloat16* __restrict__ Qh, __nv_bfloat16* __restrict__ Ql,
                 __nv_bfloat16* __restrict__ Kh, __nv_bfloat16* __restrict__ Kl,
                 __nv_bfloat16* __restrict__ Vh, __nv_bfloat16* __restrict__ Vl,
                 __nv_bfloat16* __restrict__ Wqh, __nv_bfloat16* __restrict__ Wql,
                 __nv_bfloat16* __restrict__ Wkh, __nv_bfloat16* __restrict__ Wkl,
                 __nv_bfloat16* __restrict__ Wvh, __nv_bfloat16* __restrict__ Wvl)
{
    const int z = blockIdx.z;
    const long long bigN4 = ((long long)BATCH * NQ * DM) >> 2;
    const long long wN4   = ((long long)DM * DM) >> 2;
    const float* src; __nv_bfloat16 *hi, *lo; long long n4;
    switch (z) {
        case 0: src = Q;  hi = Qh;  lo = Ql;  n4 = bigN4; break;
        case 1: src = K;  hi = Kh;  lo = Kl;  n4 = bigN4; break;
        case 2: src = V;  hi = Vh;  lo = Vl;  n4 = bigN4; break;
        case 3: src = Wq; hi = Wqh; lo = Wql; n4 = wN4;   break;
        case 4: src = Wk; hi = Wkh; lo = Wkl; n4 = wN4;   break;
        default: src = Wv; hi = Wvh; lo = Wvl; n4 = wN4;  break;
    }
    const long long i = (long long)blockIdx.x * blockDim.x + threadIdx.x;
    if (i >= n4) return;
    const float4 v = ((const float4*)src)[i];
    __nv_bfloat16 h0, h1, h2, h3, l0, l1, l2, l3;
    split1(v.x, h0, l0); split1(v.y, h1, l1); split1(v.z, h2, l2); split1(v.w, h3, l3);
    ((__nv_bfloat162*)hi)[2*i]   = __nv_bfloat162(h0, h1);
    ((__nv_bfloat162*)hi)[2*i+1] = __nv_bfloat162(h2, h3);
    ((__nv_bfloat162*)lo)[2*i]   = __nv_bfloat162(l0, l1);
    ((__nv_bfloat162*)lo)[2*i+1] = __nv_bfloat162(l2, l3);
}

// ---------------------------------------------------------------------------
// Row reductions
// ---------------------------------------------------------------------------
__device__ __forceinline__ float warp_max(float v) {
    #pragma unroll
    for (int o = 16; o; o >>= 1) v = fmaxf(v, __shfl_xor_sync(0xffffffffu, v, o));
    return v;
}
__device__ __forceinline__ float warp_sum(float v) {
    #pragma unroll
    for (int o = 16; o; o >>= 1) v += __shfl_xor_sync(0xffffffffu, v, o);
    return v;
}
__device__ __forceinline__ float block_reduce_max(float v, float* sred, int t) {
    v = warp_max(v);
    if ((t & 31) == 0) sred[t >> 5] = v;
    __syncthreads();
    if (t < 32) {
        float x = (t < 8) ? sred[t] : -INFINITY;
        #pragma unroll
        for (int o = 4; o; o >>= 1) x = fmaxf(x, __shfl_xor_sync(0xffffffffu, x, o));
        if (t == 0) sred[0] = x;
    }
    __syncthreads();
    const float r = sred[0];
    __syncthreads();
    return r;
}
__device__ __forceinline__ float block_reduce_sum(float v, float* sred, int t) {
    v = warp_sum(v);
    if ((t & 31) == 0) sred[t >> 5] = v;
    __syncthreads();
    if (t < 32) {
        float x = (t < 8) ? sred[t] : 0.f;
        #pragma unroll
        for (int o = 4; o; o >>= 1) x += __shfl_xor_sync(0xffffffffu, x, o);
        if (t == 0) sred[0] = x;
    }
    __syncthreads();
    const float r = sred[0];
    __syncthreads();
    return r;
}

// pK = softmax(Kp row) split bf16; negent[row] = sum p*logp. D = 1024, all batches.
__global__ void __launch_bounds__(256)
softmax_ent_split_rows(const float* __restrict__ X,
                       __nv_bfloat16* __restrict__ Hh, __nv_bfloat16* __restrict__ Hl,
                       float* __restrict__ negent)
{
    const float* row = X + (size_t)blockIdx.x * DM;
    const int t = threadIdx.x;
    __shared__ float sred[8];
    float x[4];
    #pragma unroll
    for (int i = 0; i < 4; i++) x[i] = row[t + 256 * i];
    float m = fmaxf(fmaxf(x[0], x[1]), fmaxf(x[2], x[3]));
    m = block_reduce_max(m, sred, t);
    float s = 0.f;
    #pragma unroll
    for (int i = 0; i < 4; i++) s += expf(x[i] - m);
    s = block_reduce_sum(s, sred, t);
    const float lse = m + logf(s);
    const size_t base = (size_t)blockIdx.x * DM + t;
    float se = 0.f;
    #pragma unroll
    for (int i = 0; i < 4; i++) {
        const float lp = x[i] - lse;
        const float p = expf(lp);
        se += p * lp;
        __nv_bfloat16 h, l;
        split1(p, h, l);
        Hh[base + 256 * i] = h;
        Hl[base + 256 * i] = l;
    }
    se = warp_sum(se);
    if ((t & 31) == 0) sred[t >> 5] = se;
    __syncthreads();
    if (t < 32) {
        float v = (t < 8) ? sred[t] : 0.f;
        #pragma unroll
        for (int o = 4; o; o >>= 1) v += __shfl_xor_sync(0xffffffffu, v, o);
        if (t == 0) negent[blockIdx.x] = v;
    }
}

// Row-normalize unnormalized exp splits: attn = E * (1/rowsum); store inv[row].
// Rows = BATCH*NQ (flat batch-major), D = 2048.
__global__ void __launch_bounds__(256)
scale_attn_rows(const __nv_bfloat16* __restrict__ Hh, const __nv_bfloat16* __restrict__ Hl,
                float* __restrict__ attn, float* __restrict__ inv)
{
    const size_t rbase = (size_t)blockIdx.x * NK;
    const int t = threadIdx.x;
    __shared__ float sred[8];
    const __nv_bfloat162* H2 = (const __nv_bfloat162*)(Hh + rbase);
    const __nv_bfloat162* L2 = (const __nv_bfloat162*)(Hl + rbase);
    float e[8];
    #pragma unroll
    for (int i = 0; i < 4; i++) {
        const __nv_bfloat162 h = H2[t + 256 * i];
        const __nv_bfloat162 l = L2[t + 256 * i];
        e[2*i]   = __bfloat162float(h.x) + __bfloat162float(l.x);
        e[2*i+1] = __bfloat162float(h.y) + __bfloat162float(l.y);
    }
    float s = e[0] + e[1] + e[2] + e[3] + e[4] + e[5] + e[6] + e[7];
    s = block_reduce_sum(s, sred, t);
    const float vi = 1.f / s;
    float2* A2 = (float2*)(attn + rbase);
    #pragma unroll
    for (int i = 0; i < 4; i++)
        A2[t + 256 * i] = make_float2(e[2*i] * vi, e[2*i+1] * vi);
    if (t == 0) inv[blockIdx.x] = vi;
}

// ---------------------------------------------------------------------------
// Launch (single stream, graph-capturable, no allocations)
// ---------------------------------------------------------------------------
extern "C" void kernel_launch(void* const* d_in, const int* in_sizes, int n_in,
                              void* d_out, int out_size)
{
    const float* Q  = (const float*)d_in[0];
    const float* K  = (const float*)d_in[1];
    const float* V  = (const float*)d_in[2];
    const float* Wq = (const float*)d_in[3];
    const float* bq = (const float*)d_in[4];
    const float* Wk = (const float*)d_in[5];
    const float* bk = (const float*)d_in[6];
    const float* Wv = (const float*)d_in[7];
    const float* bv = (const float*)d_in[8];

    float* out = (float*)d_out;
    const long long outElems  = (long long)BATCH * NQ * DM;
    const long long attnElems = (long long)BATCH * NQ * NK;

    cudaFuncSetAttribute(proj_gemm,   cudaFuncAttributeMaxDynamicSharedMemorySize, GEMM_SMEM);
    cudaFuncSetAttribute(scores_gemm, cudaFuncAttributeMaxDynamicSharedMemorySize, GEMM_SMEM);
    cudaFuncSetAttribute(out_gemm,    cudaFuncAttributeMaxDynamicSharedMemorySize, GEMM_SMEM);

    float *Kp, *negent, *invp, *attn_scratch;
    cudaGetSymbolAddress((void**)&Kp, g_Kp);
    cudaGetSymbolAddress((void**)&negent, g_negent);
    cudaGetSymbolAddress((void**)&invp, g_inv);
    cudaGetSymbolAddress((void**)&attn_scratch, g_attn);
    float* attn = ((long long)out_size >= outElems + attnElems) ? (out + outElems) : attn_scratch;

    __nv_bfloat16 *Qh, *Ql, *Kh, *Kl, *Vh, *Vl, *Wqh, *Wql, *Wkh, *Wkl, *Wvh, *Wvl;
    __nv_bfloat16 *Qph, *Qpl, *pKh, *pKl, *VpTh, *VpTl, *Ath, *Atl;
    cudaGetSymbolAddress((void**)&Qh, g_Qh);   cudaGetSymbolAddress((void**)&Ql, g_Ql);
    cudaGetSymbolAddress((void**)&Kh, g_Kh);   cudaGetSymbolAddress((void**)&Kl, g_Kl);
    cudaGetSymbolAddress((void**)&Vh, g_Vh);   cudaGetSymbolAddress((void**)&Vl, g_Vl);
    cudaGetSymbolAddress((void**)&Wqh, g_Wqh); cudaGetSymbolAddress((void**)&Wql, g_Wql);
    cudaGetSymbolAddress((void**)&Wkh, g_Wkh); cudaGetSymbolAddress((void**)&Wkl, g_Wkl);
    cudaGetSymbolAddress((void**)&Wvh, g_Wvh); cudaGetSymbolAddress((void**)&Wvl, g_Wvl);
    cudaGetSymbolAddress((void**)&Qph, g_Qph); cudaGetSymbolAddress((void**)&Qpl, g_Qpl);
    cudaGetSymbolAddress((void**)&pKh, g_pKh); cudaGetSymbolAddress((void**)&pKl, g_pKl);
    cudaGetSymbolAddress((void**)&VpTh, g_VpTh); cudaGetSymbolAddress((void**)&VpTl, g_VpTl);
    cudaGetSymbolAddress((void**)&Ath, g_Ath); cudaGetSymbolAddress((void**)&Atl, g_Atl);

    const int Mrows = BATCH * NQ;  // 8192

    // 1) input splits
    {
        const long long bigN4 = ((long long)Mrows * DM) >> 2;
        dim3 grid((unsigned)((bigN4 + 255) / 256), 1, 6);
        split_all_kernel<<<grid, 256>>>(Q, K, V, Wq, Wk, Wv,
                                        Qh, Ql, Kh, Kl, Vh, Vl,
                                        Wqh, Wql, Wkh, Wkl, Wvh, Wvl);
    }

    // 2) merged projections: Qp -> split, Kp -> fp32, Vp -> transposed split
    {
        dim3 grid(DM / 128, Mrows / 128, 3);
        proj_gemm<<<grid, 256, GEMM_SMEM>>>(Qh, Ql, Kh, Kl, Vh, Vl,
                                            Wqh, Wql, Wkh, Wkl, Wvh, Wvl,
                                            bq, bk, bv, Qph, Qpl, Kp, VpTh, VpTl);
    }

    // 3) pK split + negent
    softmax_ent_split_rows<<<Mrows, 256>>>(Kp, pKh, pKl, negent);

    // 4) E = exp(scores) as unnormalized split bf16 (no fp32 scores traffic)
    {
        dim3 grid(NK / 128, NQ / 128, BATCH);
        scores_gemm<<<grid, 256, GEMM_SMEM>>>(Qph, Qpl, pKh, pKl, negent, Ath, Atl);
    }

    // 5) normalize: attn = E/rowsum (fp32 output), inv[row] for out epilogue
    scale_attn_rows<<<Mrows, 256>>>(Ath, Atl, attn, invp);

    // 6) out = (E @ Vp) * inv
    {
        dim3 grid(DM / 128, NQ / 128, BATCH);
        out_gemm<<<grid, 256, GEMM_SMEM>>>(Ath, Atl, VpTh, VpTl, invp, out);
    }
}

// round 14
// speedup vs baseline: 1.4755x; 1.4755x over previous
#include <cuda_runtime.h>
#include <cuda_bf16.h>
#include <stdint.h>
#include <math.h>

// Problem constants
#define BATCH 4
#define NQ 2048
#define NK 2048
#define DM 1024

// ---------------------------------------------------------------------------
// Scratch (device globals)
// ---------------------------------------------------------------------------
__device__ float g_Kp[BATCH * NK * DM];
__device__ float g_Vp[BATCH * NK * DM];
__device__ float g_negent[BATCH * NK];
__device__ float g_attn[BATCH * NQ * NK];

__device__ __nv_bfloat16 g_Qh[BATCH * NQ * DM],  g_Ql[BATCH * NQ * DM];
__device__ __nv_bfloat16 g_Kh[BATCH * NK * DM],  g_Kl[BATCH * NK * DM];
__device__ __nv_bfloat16 g_Vh[BATCH * NK * DM],  g_Vl[BATCH * NK * DM];
__device__ __nv_bfloat16 g_Wqh[DM * DM], g_Wql[DM * DM];
__device__ __nv_bfloat16 g_Wkh[DM * DM], g_Wkl[DM * DM];
__device__ __nv_bfloat16 g_Wvh[DM * DM], g_Wvl[DM * DM];
__device__ __nv_bfloat16 g_Qph[BATCH * NQ * DM], g_Qpl[BATCH * NQ * DM];
__device__ __nv_bfloat16 g_pKh[BATCH * NK * DM], g_pKl[BATCH * NK * DM];
__device__ __nv_bfloat16 g_VpTh[BATCH * DM * NK], g_VpTl[BATCH * DM * NK];
__device__ __nv_bfloat16 g_Ath[BATCH * NQ * NK], g_Atl[BATCH * NQ * NK];

// ---------------------------------------------------------------------------
// Common MMA helpers
// ---------------------------------------------------------------------------
#define KC 32
#define SROW 40
#define TILEE (128 * SROW)
#define GEMM_SMEM (2 * 4 * TILEE * 2)            // 2 stages x 4 variants, bytes

__device__ __forceinline__ void ldsm_x4(uint32_t* r, uint32_t addr) {
    asm volatile("ldmatrix.sync.aligned.m8n8.x4.shared.b16 {%0,%1,%2,%3}, [%4];"
                 : "=r"(r[0]), "=r"(r[1]), "=r"(r[2]), "=r"(r[3]) : "r"(addr));
}
__device__ __forceinline__ void mma_bf16(float* c, const uint32_t* a, uint32_t b0, uint32_t b1) {
    asm volatile(
        "mma.sync.aligned.m16n8k16.row.col.f32.bf16.bf16.f32 "
        "{%0,%1,%2,%3}, {%4,%5,%6,%7}, {%8,%9}, {%0,%1,%2,%3};"
        : "+f"(c[0]), "+f"(c[1]), "+f"(c[2]), "+f"(c[3])
        : "r"(a[0]), "r"(a[1]), "r"(a[2]), "r"(a[3]), "r"(b0), "r"(b1));
}
__device__ __forceinline__ void split1(float v, __nv_bfloat16& h, __nv_bfloat16& l) {
    h = __float2bfloat16(v);
    l = __float2bfloat16(v - __bfloat162float(h));
}

// ---------------------------------------------------------------------------
// Mainloop body: acc = Ah*Bh + Al*Bh + Ah*Bl over K for CTA tile (m0,n0)
// ---------------------------------------------------------------------------
struct GemmCore {
    const __nv_bfloat16 *Ah, *Al, *Bh, *Bl;
    int m0, n0, K;

    __device__ __forceinline__ void run(__nv_bfloat16* smem, float acc[4][4][4],
                                        int tid, int lane, int wid) const
    {
        const int m_warp = (wid >> 2) * 64;
        const int n_warp = (wid & 3) * 32;
        const int nt = K / KC;
        const int lrow = tid >> 2;
        const int lc   = (tid & 3) * 8;

        auto issue = [&](int c, int stage) {
            const int k0 = c * KC;
            __nv_bfloat16* sbase = smem + stage * 4 * TILEE;
            const __nv_bfloat16* srcs[4] = {Ah, Al, Bh, Bl};
            #pragma unroll
            for (int v = 0; v < 4; v++) {
                const __nv_bfloat16* src = srcs[v];
                const int g0 = (v < 2) ? m0 : n0;
                __nv_bfloat16* dstv = sbase + v * TILEE;
                #pragma unroll
                for (int i = 0; i < 2; i++) {
                    const int row = lrow + i * 64;
                    const void* g = src + (long long)(g0 + row) * K + k0 + lc;
                    uint32_t d = (uint32_t)__cvta_generic_to_shared(dstv + row * SROW + lc);
                    asm volatile("cp.async.cg.shared.global [%0], [%1], 16;" :: "r"(d), "l"(g));
                }
            }
            asm volatile("cp.async.commit_group;");
        };

        const int ar  = lane & 15;
        const int ac8 = (lane >> 4) & 1;
        const int br  = (lane & 7) + ((lane & 16) ? 8 : 0);
        const int bc8 = (lane >> 3) & 1;

        issue(0, 0);
        if (nt > 1) issue(1, 1);

        for (int t = 0; t < nt; t++) {
            if (t + 1 < nt) { asm volatile("cp.async.wait_group 1;"); }
            else            { asm volatile("cp.async.wait_group 0;"); }
            __syncthreads();

            const int stage = t & 1;
            const uint32_t sb = (uint32_t)__cvta_generic_to_shared(smem + stage * 4 * TILEE);
            const uint32_t ab_h = sb;
            const uint32_t ab_l = sb + TILEE * 2;
            const uint32_t bb_h = sb + 2 * TILEE * 2;
            const uint32_t bb_l = sb + 3 * TILEE * 2;

            #pragma unroll
            for (int k16 = 0; k16 < 2; k16++) {
                uint32_t ah[4][4], bh[2][4];
                #pragma unroll
                for (int tm = 0; tm < 4; tm++)
                    ldsm_x4(ah[tm], ab_h + ((m_warp + tm * 16 + ar) * SROW + k16 * 16 + ac8 * 8) * 2);
                #pragma unroll
                for (int p = 0; p < 2; p++)
                    ldsm_x4(bh[p], bb_h + ((n_warp + p * 16 + br) * SROW + k16 * 16 + bc8 * 8) * 2);
                #pragma unroll
                for (int tm = 0; tm < 4; tm++)
                    #pragma unroll
                    for (int tn = 0; tn < 4; tn++)
                        mma_bf16(acc[tm][tn], ah[tm],
                                 bh[tn >> 1][(tn & 1) * 2], bh[tn >> 1][(tn & 1) * 2 + 1]);
                {
                    uint32_t al[4][4];
                    #pragma unroll
                    for (int tm = 0; tm < 4; tm++)
                        ldsm_x4(al[tm], ab_l + ((m_warp + tm * 16 + ar) * SROW + k16 * 16 + ac8 * 8) * 2);
                    #pragma unroll
                    for (int tm = 0; tm < 4; tm++)
                        #pragma unroll
                        for (int tn = 0; tn < 4; tn++)
                            mma_bf16(acc[tm][tn], al[tm],
                                     bh[tn >> 1][(tn & 1) * 2], bh[tn >> 1][(tn & 1) * 2 + 1]);
                }
                {
                    uint32_t bl[2][4];
                    #pragma unroll
                    for (int p = 0; p < 2; p++)
                        ldsm_x4(bl[p], bb_l + ((n_warp + p * 16 + br) * SROW + k16 * 16 + bc8 * 8) * 2);
                    #pragma unroll
                    for (int tm = 0; tm < 4; tm++)
                        #pragma unroll
                        for (int tn = 0; tn < 4; tn++)
                            mma_bf16(acc[tm][tn], ah[tm],
                                     bl[tn >> 1][(tn & 1) * 2], bl[tn >> 1][(tn & 1) * 2 + 1]);
                }
            }
            __syncthreads();
            if (t + 2 < nt) issue(t + 2, stage);
        }
    }
};

// ---------------------------------------------------------------------------
// Generic GEMM (scores / out), batched via z. EPI: 0 none, 2 -= vec[n].
// ---------------------------------------------------------------------------
template<int EPI>
__global__ void __launch_bounds__(256, 2)
wm_gemm(const __nv_bfloat16* __restrict__ Ah_, const __nv_bfloat16* __restrict__ Al_,
        const __nv_bfloat16* __restrict__ Bh_, const __nv_bfloat16* __restrict__ Bl_,
        const float* __restrict__ vec_, float* __restrict__ C_,
        int M, int N, int K,
        long long sA, long long sB, long long sC, long long sV)
{
    extern __shared__ __align__(16) __nv_bfloat16 smem[];
    const int tid = threadIdx.x, lane = tid & 31, wid = tid >> 5;
    const long long bz = blockIdx.z;

    GemmCore core;
    core.Ah = Ah_ + bz * sA; core.Al = Al_ + bz * sA;
    core.Bh = Bh_ + bz * sB; core.Bl = Bl_ + bz * sB;
    core.m0 = blockIdx.y * 128; core.n0 = blockIdx.x * 128; core.K = K;
    float* C = C_ + bz * sC;
    const float* vec = (EPI != 0) ? (vec_ + bz * sV) : nullptr;

    float acc[4][4][4];
    #pragma unroll
    for (int i = 0; i < 4; i++)
        #pragma unroll
        for (int j = 0; j < 4; j++)
            #pragma unroll
            for (int r = 0; r < 4; r++) acc[i][j][r] = 0.f;

    core.run(smem, acc, tid, lane, wid);

    const int m_warp = (wid >> 2) * 64;
    const int n_warp = (wid & 3) * 32;
    #pragma unroll
    for (int tm = 0; tm < 4; tm++) {
        #pragma unroll
        for (int tn = 0; tn < 4; tn++) {
            const int row = core.m0 + m_warp + tm * 16 + (lane >> 2);
            const int col = core.n0 + n_warp + tn * 8 + (lane & 3) * 2;
            float2 v0 = make_float2(acc[tm][tn][0], acc[tm][tn][1]);
            float2 v1 = make_float2(acc[tm][tn][2], acc[tm][tn][3]);
            if (EPI == 2) {
                const float2 vv = *(const float2*)&vec[col];
                v0.x -= vv.x; v0.y -= vv.y; v1.x -= vv.x; v1.y -= vv.y;
            }
            *(float2*)&C[(long long)row * N + col] = v0;
            *(float2*)&C[(long long)(row + 8) * N + col] = v1;
        }
    }
}

// ---------------------------------------------------------------------------
// Merged projection GEMM: grid.z selects {Q, K, V}. P = X @ W^T + b.
// z=0 (Q): split bf16 out. z=1/2 (K/V): fp32 out.
// ---------------------------------------------------------------------------
__global__ void __launch_bounds__(256, 2)
proj_gemm(const __nv_bfloat16* __restrict__ Qh, const __nv_bfloat16* __restrict__ Ql,
          const __nv_bfloat16* __restrict__ Kh, const __nv_bfloat16* __restrict__ Kl,
          const __nv_bfloat16* __restrict__ Vh, const __nv_bfloat16* __restrict__ Vl,
          const __nv_bfloat16* __restrict__ Wqh, const __nv_bfloat16* __restrict__ Wql,
          const __nv_bfloat16* __restrict__ Wkh, const __nv_bfloat16* __restrict__ Wkl,
          const __nv_bfloat16* __restrict__ Wvh, const __nv_bfloat16* __restrict__ Wvl,
          const float* __restrict__ bq, const float* __restrict__ bk,
          const float* __restrict__ bv,
          __nv_bfloat16* __restrict__ Qph, __nv_bfloat16* __restrict__ Qpl,
          float* __restrict__ Kp, float* __restrict__ Vp)
{
    extern __shared__ __align__(16) __nv_bfloat16 smem[];
    const int tid = threadIdx.x, lane = tid & 31, wid = tid >> 5;
    const int z = blockIdx.z;

    GemmCore core;
    const float* bias;
    if (z == 0)      { core.Ah = Qh; core.Al = Ql; core.Bh = Wqh; core.Bl = Wql; bias = bq; }
    else if (z == 1) { core.Ah = Kh; core.Al = Kl; core.Bh = Wkh; core.Bl = Wkl; bias = bk; }
    else             { core.Ah = Vh; core.Al = Vl; core.Bh = Wvh; core.Bl = Wvl; bias = bv; }
    core.m0 = blockIdx.y * 128; core.n0 = blockIdx.x * 128; core.K = DM;

    float acc[4][4][4];
    #pragma unroll
    for (int i = 0; i < 4; i++)
        #pragma unroll
        for (int j = 0; j < 4; j++)
            #pragma unroll
            for (int r = 0; r < 4; r++) acc[i][j][r] = 0.f;

    core.run(smem, acc, tid, lane, wid);

    const int m_warp = (wid >> 2) * 64;
    const int n_warp = (wid & 3) * 32;
    const int N = DM;
    float* Cf = (z == 1) ? Kp : Vp;

    #pragma unroll
    for (int tm = 0; tm < 4; tm++) {
        #pragma unroll
        for (int tn = 0; tn < 4; tn++) {
            const int row = core.m0 + m_warp + tm * 16 + (lane >> 2);
            const int col = core.n0 + n_warp + tn * 8 + (lane & 3) * 2;
            const float2 bb = *(const float2*)&bias[col];
            float2 v0 = make_float2(acc[tm][tn][0] + bb.x, acc[tm][tn][1] + bb.y);
            float2 v1 = make_float2(acc[tm][tn][2] + bb.x, acc[tm][tn][3] + bb.y);
            if (z == 0) {
                __nv_bfloat16 h0, l0, h1, l1;
                split1(v0.x, h0, l0); split1(v0.y, h1, l1);
                *(__nv_bfloat162*)&Qph[(long long)row * N + col] = __nv_bfloat162(h0, h1);
                *(__nv_bfloat162*)&Qpl[(long long)row * N + col] = __nv_bfloat162(l0, l1);
                split1(v1.x, h0, l0); split1(v1.y, h1, l1);
                *(__nv_bfloat162*)&Qph[(long long)(row + 8) * N + col] = __nv_bfloat162(h0, h1);
                *(__nv_bfloat162*)&Qpl[(long long)(row + 8) * N + col] = __nv_bfloat162(l0, l1);
            } else {
                *(float2*)&Cf[(long long)row * N + col] = v0;
                *(float2*)&Cf[(long long)(row + 8) * N + col] = v1;
            }
        }
    }
}

// ---------------------------------------------------------------------------
// Merged input splits: grid.z selects {Q, K, V, Wq, Wk, Wv}
// ---------------------------------------------------------------------------
__global__ void __launch_bounds__(256)
split_all_kernel(const float* __restrict__ Q, const float* __restrict__ K,
                 const float* __restrict__ V, const float* __restrict__ Wq,
                 const float* __restrict__ Wk, const float* __restrict__ Wv,
                 __nv_bfloat16* __restrict__ Qh, __nv_bfloat16* __restrict__ Ql,
                 __nv_bfloat16* __restrict__ Kh, __nv_bfloat16* __restrict__ Kl,
                 __nv_bfloat16* __restrict__ Vh, __nv_bfloat16* __restrict__ Vl,
                 __nv_bfloat16* __restrict__ Wqh, __nv_bfloat16* __restrict__ Wql,
                 __nv_bfloat16* __restrict__ Wkh, __nv_bfloat16* __restrict__ Wkl,
                 __nv_bfloat16* __restrict__ Wvh, __nv_bfloat16* __restrict__ Wvl)
{
    const int z = blockIdx.z;
    const long long bigN4 = ((long long)BATCH * NQ * DM) >> 2;
    const long long wN4   = ((long long)DM * DM) >> 2;
    const float* src; __nv_bfloat16 *hi, *lo; long long n4;
    switch (z) {
        case 0: src = Q;  hi = Qh;  lo = Ql;  n4 = bigN4; break;
        case 1: src = K;  hi = Kh;  lo = Kl;  n4 = bigN4; break;
        case 2: src = V;  hi = Vh;  lo = Vl;  n4 = bigN4; break;
        case 3: src = Wq; hi = Wqh; lo = Wql; n4 = wN4;   break;
        case 4: src = Wk; hi = Wkh; lo = Wkl; n4 = wN4;   break;
        default: src = Wv; hi = Wvh; lo = Wvl; n4 = wN4;  break;
    }
    const long long i = (long long)blockIdx.x * blockDim.x + threadIdx.x;
    if (i >= n4) return;
    const float4 v = ((const float4*)src)[i];
    __nv_bfloat16 h0, h1, h2, h3, l0, l1, l2, l3;
    split1(v.x, h0, l0); split1(v.y, h1, l1); split1(v.z, h2, l2); split1(v.w, h3, l3);
    ((__nv_bfloat162*)hi)[2*i]   = __nv_bfloat162(h0, h1);
    ((__nv_bfloat162*)hi)[2*i+1] = __nv_bfloat162(h2, h3);
    ((__nv_bfloat162*)lo)[2*i]   = __nv_bfloat162(l0, l1);
    ((__nv_bfloat162*)lo)[2*i+1] = __nv_bfloat162(l2, l3);
}

// ---------------------------------------------------------------------------
// Row reductions
// ---------------------------------------------------------------------------
__device__ __forceinline__ float warp_max(float v) {
    #pragma unroll
    for (int o = 16; o; o >>= 1) v = fmaxf(v, __shfl_xor_sync(0xffffffffu, v, o));
    return v;
}
__device__ __forceinline__ float warp_sum(float v) {
    #pragma unroll
    for (int o = 16; o; o >>= 1) v += __shfl_xor_sync(0xffffffffu, v, o);
    return v;
}
__device__ __forceinline__ float block_reduce_max(float v, float* sred, int t) {
    v = warp_max(v);
    if ((t & 31) == 0) sred[t >> 5] = v;
    __syncthreads();
    if (t < 32) {
        float x = (t < 8) ? sred[t] : -INFINITY;
        #pragma unroll
        for (int o = 4; o; o >>= 1) x = fmaxf(x, __shfl_xor_sync(0xffffffffu, x, o));
        if (t == 0) sred[0] = x;
    }
    __syncthreads();
    const float r = sred[0];
    __syncthreads();
    return r;
}
__device__ __forceinline__ float block_reduce_sum(float v, float* sred, int t) {
    v = warp_sum(v);
    if ((t & 31) == 0) sred[t >> 5] = v;
    __syncthreads();
    if (t < 32) {
        float x = (t < 8) ? sred[t] : 0.f;
        #pragma unroll
        for (int o = 4; o; o >>= 1) x += __shfl_xor_sync(0xffffffffu, x, o);
        if (t == 0) sred[0] = x;
    }
    __syncthreads();
    const float r = sred[0];
    __syncthreads();
    return r;
}

// ---------------------------------------------------------------------------
// Fused post-projection elementwise: one launch, two independent jobs.
//   blockIdx.x < Mrows               : softmax_ent on Kp row -> pK splits + negent
//   blockIdx.x >= Mrows              : 32x32 transpose tile of Vp -> VpT splits
// Both jobs use 256 threads.
// ---------------------------------------------------------------------------
__global__ void __launch_bounds__(256)
ent_and_transpose_kernel(const float* __restrict__ Kp,
                         __nv_bfloat16* __restrict__ pKh, __nv_bfloat16* __restrict__ pKl,
                         float* __restrict__ negent,
                         const float* __restrict__ Vp,
                         __nv_bfloat16* __restrict__ VpTh, __nv_bfloat16* __restrict__ VpTl)
{
    const int Mrows = BATCH * NK;   // 8192 ent rows
    const int t = threadIdx.x;

    if ((int)blockIdx.x < Mrows) {
        // ---- softmax + entropy on one Kp row ----
        const int r = blockIdx.x;
        const float* row = Kp + (size_t)r * DM;
        __shared__ float sred[8];
        float x[4];
        #pragma unroll
        for (int i = 0; i < 4; i++) x[i] = row[t + 256 * i];
        float m = fmaxf(fmaxf(x[0], x[1]), fmaxf(x[2], x[3]));
        m = block_reduce_max(m, sred, t);
        float s = 0.f;
        #pragma unroll
        for (int i = 0; i < 4; i++) s += expf(x[i] - m);
        s = block_reduce_sum(s, sred, t);
        const float lse = m + logf(s);
        const size_t base = (size_t)r * DM + t;
        float se = 0.f;
        #pragma unroll
        for (int i = 0; i < 4; i++) {
            const float lp = x[i] - lse;
            const float p = expf(lp);
            se += p * lp;
            __nv_bfloat16 h, l;
            split1(p, h, l);
            pKh[base + 256 * i] = h;
            pKl[base + 256 * i] = l;
        }
        se = warp_sum(se);
        if ((t & 31) == 0) sred[t >> 5] = se;
        __syncthreads();
        if (t < 32) {
            float v = (t < 8) ? sred[t] : 0.f;
            #pragma unroll
            for (int o = 4; o; o >>= 1) v += __shfl_xor_sync(0xffffffffu, v, o);
            if (t == 0) negent[r] = v;
        }
    } else {
        // ---- 32x32 transpose+split tile of Vp ----
        __shared__ float tile[32][33];
        const int idx = blockIdx.x - Mrows;        // 0 .. BATCH*2048-1
        const int b   = idx >> 11;                 // 2048 tiles per batch
        const int rem = idx & 2047;
        const int x0  = (rem & 31) * 32;           // headdim tile (DM/32 = 32)
        const int y0  = (rem >> 5) * 32;           // token tile   (NK/32 = 64)
        const int tx = t & 31, ty = t >> 5;        // (32, 8)
        const float* S = Vp + (long long)b * NK * DM;
        #pragma unroll
        for (int j = 0; j < 32; j += 8)
            tile[ty + j][tx] = S[(long long)(y0 + ty + j) * DM + x0 + tx];
        __syncthreads();
        __nv_bfloat16* Hh = VpTh + (long long)b * DM * NK;
        __nv_bfloat16* Hl = VpTl + (long long)b * DM * NK;
        #pragma unroll
        for (int j = 0; j < 32; j += 8) {
            const float v = tile[tx][ty + j];
            const int orow = x0 + ty + j;
            const int ocol = y0 + tx;
            __nv_bfloat16 h, l;
            split1(v, h, l);
            Hh[(long long)orow * NK + ocol] = h;
            Hl[(long long)orow * NK + ocol] = l;
        }
    }
}

// attn = softmax(scores row) in place (fp32) + split bf16. D = 2048.
__global__ void __launch_bounds__(256)
attn_softmax_split_rows(float* __restrict__ X,
                        __nv_bfloat16* __restrict__ Hh, __nv_bfloat16* __restrict__ Hl)
{
    float* row = X + (size_t)blockIdx.x * NK;
    const int t = threadIdx.x;
    __shared__ float sred[8];
    float x[8];
    #pragma unroll
    for (int i = 0; i < 8; i++) x[i] = row[t + 256 * i];
    float m = -INFINITY;
    #pragma unroll
    for (int i = 0; i < 8; i++) m = fmaxf(m, x[i]);
    m = block_reduce_max(m, sred, t);
    float ex[8];
    float s = 0.f;
    #pragma unroll
    for (int i = 0; i < 8; i++) { ex[i] = expf(x[i] - m); s += ex[i]; }
    s = block_reduce_sum(s, sred, t);
    const float inv = 1.f / s;
    const size_t base = (size_t)blockIdx.x * NK + t;
    #pragma unroll
    for (int i = 0; i < 8; i++) {
        const float p = ex[i] * inv;
        row[t + 256 * i] = p;
        __nv_bfloat16 h, l;
        split1(p, h, l);
        Hh[base + 256 * i] = h;
        Hl[base + 256 * i] = l;
    }
}

// ---------------------------------------------------------------------------
// Launch (single stream, graph-capturable, no allocations)
// ---------------------------------------------------------------------------
extern "C" void kernel_launch(void* const* d_in, const int* in_sizes, int n_in,
                              void* d_out, int out_size)
{
    const float* Q  = (const float*)d_in[0];
    const float* K  = (const float*)d_in[1];
    const float* V  = (const float*)d_in[2];
    const float* Wq = (const float*)d_in[3];
    const float* bq = (const float*)d_in[4];
    const float* Wk = (const float*)d_in[5];
    const float* bk = (const float*)d_in[6];
    const float* Wv = (const float*)d_in[7];
    const float* bv = (const float*)d_in[8];

    float* out = (float*)d_out;
    const long long outElems  = (long long)BATCH * NQ * DM;
    const long long attnElems = (long long)BATCH * NQ * NK;

    cudaFuncSetAttribute(wm_gemm<0>, cudaFuncAttributeMaxDynamicSharedMemorySize, GEMM_SMEM);
    cudaFuncSetAttribute(wm_gemm<2>, cudaFuncAttributeMaxDynamicSharedMemorySize, GEMM_SMEM);
    cudaFuncSetAttribute(proj_gemm, cudaFuncAttributeMaxDynamicSharedMemorySize, GEMM_SMEM);

    float *Kp, *Vp, *negent, *attn_scratch;
    cudaGetSymbolAddress((void**)&Kp, g_Kp);
    cudaGetSymbolAddress((void**)&Vp, g_Vp);
    cudaGetSymbolAddress((void**)&negent, g_negent);
    cudaGetSymbolAddress((void**)&attn_scratch, g_attn);
    float* attn = ((long long)out_size >= outElems + attnElems) ? (out + outElems) : attn_scratch;

    __nv_bfloat16 *Qh, *Ql, *Kh, *Kl, *Vh, *Vl, *Wqh, *Wql, *Wkh, *Wkl, *Wvh, *Wvl;
    __nv_bfloat16 *Qph, *Qpl, *pKh, *pKl, *VpTh, *VpTl, *Ath, *Atl;
    cudaGetSymbolAddress((void**)&Qh, g_Qh);   cudaGetSymbolAddress((void**)&Ql, g_Ql);
    cudaGetSymbolAddress((void**)&Kh, g_Kh);   cudaGetSymbolAddress((void**)&Kl, g_Kl);
    cudaGetSymbolAddress((void**)&Vh, g_Vh);   cudaGetSymbolAddress((void**)&Vl, g_Vl);
    cudaGetSymbolAddress((void**)&Wqh, g_Wqh); cudaGetSymbolAddress((void**)&Wql, g_Wql);
    cudaGetSymbolAddress((void**)&Wkh, g_Wkh); cudaGetSymbolAddress((void**)&Wkl, g_Wkl);
    cudaGetSymbolAddress((void**)&Wvh, g_Wvh); cudaGetSymbolAddress((void**)&Wvl, g_Wvl);
    cudaGetSymbolAddress((void**)&Qph, g_Qph); cudaGetSymbolAddress((void**)&Qpl, g_Qpl);
    cudaGetSymbolAddress((void**)&pKh, g_pKh); cudaGetSymbolAddress((void**)&pKl, g_pKl);
    cudaGetSymbolAddress((void**)&VpTh, g_VpTh); cudaGetSymbolAddress((void**)&VpTl, g_VpTl);
    cudaGetSymbolAddress((void**)&Ath, g_Ath); cudaGetSymbolAddress((void**)&Atl, g_Atl);

    const int Mrows = BATCH * NQ;  // 8192

    // 1) input splits (one launch)
    {
        const long long bigN4 = ((long long)Mrows * DM) >> 2;
        dim3 grid((unsigned)((bigN4 + 255) / 256), 1, 6);
        split_all_kernel<<<grid, 256>>>(Q, K, V, Wq, Wk, Wv,
                                        Qh, Ql, Kh, Kl, Vh, Vl,
                                        Wqh, Wql, Wkh, Wkl, Wvh, Wvl);
    }

    // 2) merged projections; Q epilogue writes split bf16 directly
    {
        dim3 grid(DM / 128, Mrows / 128, 3);
        proj_gemm<<<grid, 256, GEMM_SMEM>>>(Qh, Ql, Kh, Kl, Vh, Vl,
                                            Wqh, Wql, Wkh, Wkl, Wvh, Wvl,
                                            bq, bk, bv, Qph, Qpl, Kp, Vp);
    }

    // 3) fused: pK softmax+entropy splits AND Vp transpose splits, one launch
    {
        const unsigned nblocks = (unsigned)(Mrows + BATCH * 2048);  // 8192 + 8192
        ent_and_transpose_kernel<<<nblocks, 256>>>(Kp, pKh, pKl, negent,
                                                   Vp, VpTh, VpTl);
    }

    // 4) scores[b,i,j] = Qp_i . pK_j - negent[j]   (lse_i shift drops in softmax)
    {
        dim3 grid(NK / 128, NQ / 128, BATCH);
        wm_gemm<2><<<grid, 256, GEMM_SMEM>>>(
            Qph, Qpl, pKh, pKl, negent, attn, NQ, NK, DM,
            (long long)NQ * DM, (long long)NK * DM, (long long)NQ * NK, (long long)NK);
    }

    // 5) attn = softmax(scores) fp32 + split bf16
    attn_softmax_split_rows<<<BATCH * NQ, 256>>>(attn, Ath, Atl);

    // 6) out = attn @ Vp (via VpT, NT form)
    {
        dim3 grid(DM / 128, NQ / 128, BATCH);
        wm_gemm<0><<<grid, 256, GEMM_SMEM>>>(
            Ath, Atl, VpTh, VpTl, nullptr, out, NQ, DM, NK,
            (long long)NQ * NK, (long long)DM * NK, (long long)NQ * DM, 0);
    }
}

// round 15
// speedup vs baseline: 1.5947x; 1.0808x over previous
#include <cuda_runtime.h>
#include <cuda_bf16.h>
#include <stdint.h>
#include <math.h>

// Problem constants
#define BATCH 4
#define NQ 2048
#define NK 2048
#define DM 1024

// ---------------------------------------------------------------------------
// Scratch (device globals)
// ---------------------------------------------------------------------------
__device__ float g_Kp[BATCH * NK * DM];
__device__ float g_Vp[BATCH * NK * DM];
__device__ float g_negent[BATCH * NK];
__device__ float g_attn[BATCH * NQ * NK];

__device__ __nv_bfloat16 g_Qh[BATCH * NQ * DM],  g_Ql[BATCH * NQ * DM];
__device__ __nv_bfloat16 g_Kh[BATCH * NK * DM],  g_Kl[BATCH * NK * DM];
__device__ __nv_bfloat16 g_Vh[BATCH * NK * DM],  g_Vl[BATCH * NK * DM];
__device__ __nv_bfloat16 g_Wqh[DM * DM], g_Wql[DM * DM];
__device__ __nv_bfloat16 g_Wkh[DM * DM], g_Wkl[DM * DM];
__device__ __nv_bfloat16 g_Wvh[DM * DM], g_Wvl[DM * DM];
__device__ __nv_bfloat16 g_Qph[BATCH * NQ * DM], g_Qpl[BATCH * NQ * DM];
__device__ __nv_bfloat16 g_pKh[BATCH * NK * DM];
__device__ __nv_bfloat16 g_VpTh[BATCH * DM * NK], g_VpTl[BATCH * DM * NK];
__device__ __nv_bfloat16 g_Ath[BATCH * NQ * NK], g_Atl[BATCH * NQ * NK];

// ---------------------------------------------------------------------------
// Common MMA helpers
// ---------------------------------------------------------------------------
#define KC 32
#define SROW 40
#define TILEE (128 * SROW)
#define GEMM_SMEM  (2 * 4 * TILEE * 2)           // 3-term path: 2 stages x 4 variants
#define GEMM_SMEM2 (2 * 3 * TILEE * 2)           // 2-term path: 2 stages x 3 variants

__device__ __forceinline__ void ldsm_x4(uint32_t* r, uint32_t addr) {
    asm volatile("ldmatrix.sync.aligned.m8n8.x4.shared.b16 {%0,%1,%2,%3}, [%4];"
                 : "=r"(r[0]), "=r"(r[1]), "=r"(r[2]), "=r"(r[3]) : "r"(addr));
}
__device__ __forceinline__ void mma_bf16(float* c, const uint32_t* a, uint32_t b0, uint32_t b1) {
    asm volatile(
        "mma.sync.aligned.m16n8k16.row.col.f32.bf16.bf16.f32 "
        "{%0,%1,%2,%3}, {%4,%5,%6,%7}, {%8,%9}, {%0,%1,%2,%3};"
        : "+f"(c[0]), "+f"(c[1]), "+f"(c[2]), "+f"(c[3])
        : "r"(a[0]), "r"(a[1]), "r"(a[2]), "r"(a[3]), "r"(b0), "r"(b1));
}
__device__ __forceinline__ void split1(float v, __nv_bfloat16& h, __nv_bfloat16& l) {
    h = __float2bfloat16(v);
    l = __float2bfloat16(v - __bfloat162float(h));
}

// ---------------------------------------------------------------------------
// Mainloop body.
// NTERMS=3: acc = Ah*Bh + Al*Bh + Ah*Bl   (variants Ah, Al, Bh, Bl)
// NTERMS=2: acc = Ah*Bh + Al*Bh           (variants Ah, Al, Bh — Bl unused)
// ---------------------------------------------------------------------------
struct GemmCore {
    const __nv_bfloat16 *Ah, *Al, *Bh, *Bl;
    int m0, n0, K;

    template<int NTERMS>
    __device__ __forceinline__ void run(__nv_bfloat16* smem, float acc[4][4][4],
                                        int tid, int lane, int wid) const
    {
        const int NVAR = (NTERMS == 3) ? 4 : 3;
        const int m_warp = (wid >> 2) * 64;
        const int n_warp = (wid & 3) * 32;
        const int nt = K / KC;
        const int lrow = tid >> 2;
        const int lc   = (tid & 3) * 8;

        auto issue = [&](int c, int stage) {
            const int k0 = c * KC;
            __nv_bfloat16* sbase = smem + stage * NVAR * TILEE;
            const __nv_bfloat16* srcs[4] = {Ah, Al, Bh, Bl};
            #pragma unroll
            for (int v = 0; v < NVAR; v++) {
                const __nv_bfloat16* src = srcs[v];
                const int g0 = (v < 2) ? m0 : n0;
                __nv_bfloat16* dstv = sbase + v * TILEE;
                #pragma unroll
                for (int i = 0; i < 2; i++) {
                    const int row = lrow + i * 64;
                    const void* g = src + (long long)(g0 + row) * K + k0 + lc;
                    uint32_t d = (uint32_t)__cvta_generic_to_shared(dstv + row * SROW + lc);
                    asm volatile("cp.async.cg.shared.global [%0], [%1], 16;" :: "r"(d), "l"(g));
                }
            }
            asm volatile("cp.async.commit_group;");
        };

        const int ar  = lane & 15;
        const int ac8 = (lane >> 4) & 1;
        const int br  = (lane & 7) + ((lane & 16) ? 8 : 0);
        const int bc8 = (lane >> 3) & 1;

        issue(0, 0);
        if (nt > 1) issue(1, 1);

        for (int t = 0; t < nt; t++) {
            if (t + 1 < nt) { asm volatile("cp.async.wait_group 1;"); }
            else            { asm volatile("cp.async.wait_group 0;"); }
            __syncthreads();

            const int stage = t & 1;
            const uint32_t sb = (uint32_t)__cvta_generic_to_shared(smem + stage * NVAR * TILEE);
            const uint32_t ab_h = sb;
            const uint32_t ab_l = sb + TILEE * 2;
            const uint32_t bb_h = sb + 2 * TILEE * 2;
            const uint32_t bb_l = sb + 3 * TILEE * 2;

            #pragma unroll
            for (int k16 = 0; k16 < 2; k16++) {
                uint32_t ah[4][4], bh[2][4];
                #pragma unroll
                for (int tm = 0; tm < 4; tm++)
                    ldsm_x4(ah[tm], ab_h + ((m_warp + tm * 16 + ar) * SROW + k16 * 16 + ac8 * 8) * 2);
                #pragma unroll
                for (int p = 0; p < 2; p++)
                    ldsm_x4(bh[p], bb_h + ((n_warp + p * 16 + br) * SROW + k16 * 16 + bc8 * 8) * 2);
                // term 0: Ah * Bh
                #pragma unroll
                for (int tm = 0; tm < 4; tm++)
                    #pragma unroll
                    for (int tn = 0; tn < 4; tn++)
                        mma_bf16(acc[tm][tn], ah[tm],
                                 bh[tn >> 1][(tn & 1) * 2], bh[tn >> 1][(tn & 1) * 2 + 1]);
                // term 1: Al * Bh
                {
                    uint32_t al[4][4];
                    #pragma unroll
                    for (int tm = 0; tm < 4; tm++)
                        ldsm_x4(al[tm], ab_l + ((m_warp + tm * 16 + ar) * SROW + k16 * 16 + ac8 * 8) * 2);
                    #pragma unroll
                    for (int tm = 0; tm < 4; tm++)
                        #pragma unroll
                        for (int tn = 0; tn < 4; tn++)
                            mma_bf16(acc[tm][tn], al[tm],
                                     bh[tn >> 1][(tn & 1) * 2], bh[tn >> 1][(tn & 1) * 2 + 1]);
                }
                // term 2: Ah * Bl (3-term only)
                if (NTERMS == 3) {
                    uint32_t bl[2][4];
                    #pragma unroll
                    for (int p = 0; p < 2; p++)
                        ldsm_x4(bl[p], bb_l + ((n_warp + p * 16 + br) * SROW + k16 * 16 + bc8 * 8) * 2);
                    #pragma unroll
                    for (int tm = 0; tm < 4; tm++)
                        #pragma unroll
                        for (int tn = 0; tn < 4; tn++)
                            mma_bf16(acc[tm][tn], ah[tm],
                                     bl[tn >> 1][(tn & 1) * 2], bl[tn >> 1][(tn & 1) * 2 + 1]);
                }
            }
            __syncthreads();
            if (t + 2 < nt) issue(t + 2, stage);
        }
    }
};

// ---------------------------------------------------------------------------
// Generic GEMM (scores / out), batched via z. EPI: 0 none, 2 -= vec[n].
// NTERMS: 3 full split, 2 drops the A*Bl cross term (B treated as hi-only).
// ---------------------------------------------------------------------------
template<int EPI, int NTERMS>
__global__ void __launch_bounds__(256, 2)
wm_gemm(const __nv_bfloat16* __restrict__ Ah_, const __nv_bfloat16* __restrict__ Al_,
        const __nv_bfloat16* __restrict__ Bh_, const __nv_bfloat16* __restrict__ Bl_,
        const float* __restrict__ vec_, float* __restrict__ C_,
        int M, int N, int K,
        long long sA, long long sB, long long sC, long long sV)
{
    extern __shared__ __align__(16) __nv_bfloat16 smem[];
    const int tid = threadIdx.x, lane = tid & 31, wid = tid >> 5;
    const long long bz = blockIdx.z;

    GemmCore core;
    core.Ah = Ah_ + bz * sA; core.Al = Al_ + bz * sA;
    core.Bh = Bh_ + bz * sB; core.Bl = (NTERMS == 3) ? (Bl_ + bz * sB) : core.Bh;
    core.m0 = blockIdx.y * 128; core.n0 = blockIdx.x * 128; core.K = K;
    float* C = C_ + bz * sC;
    const float* vec = (EPI != 0) ? (vec_ + bz * sV) : nullptr;

    float acc[4][4][4];
    #pragma unroll
    for (int i = 0; i < 4; i++)
        #pragma unroll
        for (int j = 0; j < 4; j++)
            #pragma unroll
            for (int r = 0; r < 4; r++) acc[i][j][r] = 0.f;

    core.run<NTERMS>(smem, acc, tid, lane, wid);

    const int m_warp = (wid >> 2) * 64;
    const int n_warp = (wid & 3) * 32;
    #pragma unroll
    for (int tm = 0; tm < 4; tm++) {
        #pragma unroll
        for (int tn = 0; tn < 4; tn++) {
            const int row = core.m0 + m_warp + tm * 16 + (lane >> 2);
            const int col = core.n0 + n_warp + tn * 8 + (lane & 3) * 2;
            float2 v0 = make_float2(acc[tm][tn][0], acc[tm][tn][1]);
            float2 v1 = make_float2(acc[tm][tn][2], acc[tm][tn][3]);
            if (EPI == 2) {
                const float2 vv = *(const float2*)&vec[col];
                v0.x -= vv.x; v0.y -= vv.y; v1.x -= vv.x; v1.y -= vv.y;
            }
            *(float2*)&C[(long long)row * N + col] = v0;
            *(float2*)&C[(long long)(row + 8) * N + col] = v1;
        }
    }
}

// ---------------------------------------------------------------------------
// Merged projection GEMM: grid.z selects {Q, K, V}. P = X @ W^T + b.
// z=0 (Q): split bf16 out. z=1/2 (K/V): fp32 out.
// ---------------------------------------------------------------------------
__global__ void __launch_bounds__(256, 2)
proj_gemm(const __nv_bfloat16* __restrict__ Qh, const __nv_bfloat16* __restrict__ Ql,
          const __nv_bfloat16* __restrict__ Kh, const __nv_bfloat16* __restrict__ Kl,
          const __nv_bfloat16* __restrict__ Vh, const __nv_bfloat16* __restrict__ Vl,
          const __nv_bfloat16* __restrict__ Wqh, const __nv_bfloat16* __restrict__ Wql,
          const __nv_bfloat16* __restrict__ Wkh, const __nv_bfloat16* __restrict__ Wkl,
          const __nv_bfloat16* __restrict__ Wvh, const __nv_bfloat16* __restrict__ Wvl,
          const float* __restrict__ bq, const float* __restrict__ bk,
          const float* __restrict__ bv,
          __nv_bfloat16* __restrict__ Qph, __nv_bfloat16* __restrict__ Qpl,
          float* __restrict__ Kp, float* __restrict__ Vp)
{
    extern __shared__ __align__(16) __nv_bfloat16 smem[];
    const int tid = threadIdx.x, lane = tid & 31, wid = tid >> 5;
    const int z = blockIdx.z;

    GemmCore core;
    const float* bias;
    if (z == 0)      { core.Ah = Qh; core.Al = Ql; core.Bh = Wqh; core.Bl = Wql; bias = bq; }
    else if (z == 1) { core.Ah = Kh; core.Al = Kl; core.Bh = Wkh; core.Bl = Wkl; bias = bk; }
    else             { core.Ah = Vh; core.Al = Vl; core.Bh = Wvh; core.Bl = Wvl; bias = bv; }
    core.m0 = blockIdx.y * 128; core.n0 = blockIdx.x * 128; core.K = DM;

    float acc[4][4][4];
    #pragma unroll
    for (int i = 0; i < 4; i++)
        #pragma unroll
        for (int j = 0; j < 4; j++)
            #pragma unroll
            for (int r = 0; r < 4; r++) acc[i][j][r] = 0.f;

    core.run<3>(smem, acc, tid, lane, wid);

    const int m_warp = (wid >> 2) * 64;
    const int n_warp = (wid & 3) * 32;
    const int N = DM;
    float* Cf = (z == 1) ? Kp : Vp;

    #pragma unroll
    for (int tm = 0; tm < 4; tm++) {
        #pragma unroll
        for (int tn = 0; tn < 4; tn++) {
            const int row = core.m0 + m_warp + tm * 16 + (lane >> 2);
            const int col = core.n0 + n_warp + tn * 8 + (lane & 3) * 2;
            const float2 bb = *(const float2*)&bias[col];
            float2 v0 = make_float2(acc[tm][tn][0] + bb.x, acc[tm][tn][1] + bb.y);
            float2 v1 = make_float2(acc[tm][tn][2] + bb.x, acc[tm][tn][3] + bb.y);
            if (z == 0) {
                __nv_bfloat16 h0, l0, h1, l1;
                split1(v0.x, h0, l0); split1(v0.y, h1, l1);
                *(__nv_bfloat162*)&Qph[(long long)row * N + col] = __nv_bfloat162(h0, h1);
                *(__nv_bfloat162*)&Qpl[(long long)row * N + col] = __nv_bfloat162(l0, l1);
                split1(v1.x, h0, l0); split1(v1.y, h1, l1);
                *(__nv_bfloat162*)&Qph[(long long)(row + 8) * N + col] = __nv_bfloat162(h0, h1);
                *(__nv_bfloat162*)&Qpl[(long long)(row + 8) * N + col] = __nv_bfloat162(l0, l1);
            } else {
                *(float2*)&Cf[(long long)row * N + col] = v0;
                *(float2*)&Cf[(long long)(row + 8) * N + col] = v1;
            }
        }
    }
}

// ---------------------------------------------------------------------------
// Merged input splits: grid.z selects {Q, K, V, Wq, Wk, Wv}
// ---------------------------------------------------------------------------
__global__ void __launch_bounds__(256)
split_all_kernel(const float* __restrict__ Q, const float* __restrict__ K,
                 const float* __restrict__ V, const float* __restrict__ Wq,
                 const float* __restrict__ Wk, const float* __restrict__ Wv,
                 __nv_bfloat16* __restrict__ Qh, __nv_bfloat16* __restrict__ Ql,
                 __nv_bfloat16* __restrict__ Kh, __nv_bfloat16* __restrict__ Kl,
                 __nv_bfloat16* __restrict__ Vh, __nv_bfloat16* __restrict__ Vl,
                 __nv_bfloat16* __restrict__ Wqh, __nv_bfloat16* __restrict__ Wql,
                 __nv_bfloat16* __restrict__ Wkh, __nv_bfloat16* __restrict__ Wkl,
                 __nv_bfloat16* __restrict__ Wvh, __nv_bfloat16* __restrict__ Wvl)
{
    const int z = blockIdx.z;
    const long long bigN4 = ((long long)BATCH * NQ * DM) >> 2;
    const long long wN4   = ((long long)DM * DM) >> 2;
    const float* src; __nv_bfloat16 *hi, *lo; long long n4;
    switch (z) {
        case 0: src = Q;  hi = Qh;  lo = Ql;  n4 = bigN4; break;
        case 1: src = K;  hi = Kh;  lo = Kl;  n4 = bigN4; break;
        case 2: src = V;  hi = Vh;  lo = Vl;  n4 = bigN4; break;
        case 3: src = Wq; hi = Wqh; lo = Wql; n4 = wN4;   break;
        case 4: src = Wk; hi = Wkh; lo = Wkl; n4 = wN4;   break;
        default: src = Wv; hi = Wvh; lo = Wvl; n4 = wN4;  break;
    }
    const long long i = (long long)blockIdx.x * blockDim.x + threadIdx.x;
    if (i >= n4) return;
    const float4 v = ((const float4*)src)[i];
    __nv_bfloat16 h0, h1, h2, h3, l0, l1, l2, l3;
    split1(v.x, h0, l0); split1(v.y, h1, l1); split1(v.z, h2, l2); split1(v.w, h3, l3);
    ((__nv_bfloat162*)hi)[2*i]   = __nv_bfloat162(h0, h1);
    ((__nv_bfloat162*)hi)[2*i+1] = __nv_bfloat162(h2, h3);
    ((__nv_bfloat162*)lo)[2*i]   = __nv_bfloat162(l0, l1);
    ((__nv_bfloat162*)lo)[2*i+1] = __nv_bfloat162(l2, l3);
}

// ---------------------------------------------------------------------------
// Row reductions
// ---------------------------------------------------------------------------
__device__ __forceinline__ float warp_max(float v) {
    #pragma unroll
    for (int o = 16; o; o >>= 1) v = fmaxf(v, __shfl_xor_sync(0xffffffffu, v, o));
    return v;
}
__device__ __forceinline__ float warp_sum(float v) {
    #pragma unroll
    for (int o = 16; o; o >>= 1) v += __shfl_xor_sync(0xffffffffu, v, o);
    return v;
}
__device__ __forceinline__ float block_reduce_max(float v, float* sred, int t) {
    v = warp_max(v);
    if ((t & 31) == 0) sred[t >> 5] = v;
    __syncthreads();
    if (t < 32) {
        float x = (t < 8) ? sred[t] : -INFINITY;
        #pragma unroll
        for (int o = 4; o; o >>= 1) x = fmaxf(x, __shfl_xor_sync(0xffffffffu, x, o));
        if (t == 0) sred[0] = x;
    }
    __syncthreads();
    const float r = sred[0];
    __syncthreads();
    return r;
}
__device__ __forceinline__ float block_reduce_sum(float v, float* sred, int t) {
    v = warp_sum(v);
    if ((t & 31) == 0) sred[t >> 5] = v;
    __syncthreads();
    if (t < 32) {
        float x = (t < 8) ? sred[t] : 0.f;
        #pragma unroll
        for (int o = 4; o; o >>= 1) x += __shfl_xor_sync(0xffffffffu, x, o);
        if (t == 0) sred[0] = x;
    }
    __syncthreads();
    const float r = sred[0];
    __syncthreads();
    return r;
}

// ---------------------------------------------------------------------------
// Fused post-projection elementwise: one launch, two independent jobs.
//   blockIdx.x < Mrows : softmax_ent on Kp row -> pK hi split + negent
//   blockIdx.x >= Mrows: 32x32 transpose tile of Vp -> VpT splits
// ---------------------------------------------------------------------------
__global__ void __launch_bounds__(256)
ent_and_transpose_kernel(const float* __restrict__ Kp,
                         __nv_bfloat16* __restrict__ pKh,
                         float* __restrict__ negent,
                         const float* __restrict__ Vp,
                         __nv_bfloat16* __restrict__ VpTh, __nv_bfloat16* __restrict__ VpTl)
{
    const int Mrows = BATCH * NK;   // 8192 ent rows
    const int t = threadIdx.x;

    if ((int)blockIdx.x < Mrows) {
        const int r = blockIdx.x;
        const float* row = Kp + (size_t)r * DM;
        __shared__ float sred[8];
        float x[4];
        #pragma unroll
        for (int i = 0; i < 4; i++) x[i] = row[t + 256 * i];
        float m = fmaxf(fmaxf(x[0], x[1]), fmaxf(x[2], x[3]));
        m = block_reduce_max(m, sred, t);
        float s = 0.f;
        #pragma unroll
        for (int i = 0; i < 4; i++) s += expf(x[i] - m);
        s = block_reduce_sum(s, sred, t);
        const float lse = m + logf(s);
        const size_t base = (size_t)r * DM + t;
        float se = 0.f;
        #pragma unroll
        for (int i = 0; i < 4; i++) {
            const float lp = x[i] - lse;
            const float p = expf(lp);
            se += p * lp;
            pKh[base + 256 * i] = __float2bfloat16(p);
        }
        se = warp_sum(se);
        if ((t & 31) == 0) sred[t >> 5] = se;
        __syncthreads();
        if (t < 32) {
            float v = (t < 8) ? sred[t] : 0.f;
            #pragma unroll
            for (int o = 4; o; o >>= 1) v += __shfl_xor_sync(0xffffffffu, v, o);
            if (t == 0) negent[r] = v;
        }
    } else {
        __shared__ float tile[32][33];
        const int idx = blockIdx.x - Mrows;
        const int b   = idx >> 11;
        const int rem = idx & 2047;
        const int x0  = (rem & 31) * 32;
        const int y0  = (rem >> 5) * 32;
        const int tx = t & 31, ty = t >> 5;
        const float* S = Vp + (long long)b * NK * DM;
        #pragma unroll
        for (int j = 0; j < 32; j += 8)
            tile[ty + j][tx] = S[(long long)(y0 + ty + j) * DM + x0 + tx];
        __syncthreads();
        __nv_bfloat16* Hh = VpTh + (long long)b * DM * NK;
        __nv_bfloat16* Hl = VpTl + (long long)b * DM * NK;
        #pragma unroll
        for (int j = 0; j < 32; j += 8) {
            const float v = tile[tx][ty + j];
            const int orow = x0 + ty + j;
            const int ocol = y0 + tx;
            __nv_bfloat16 h, l;
            split1(v, h, l);
            Hh[(long long)orow * NK + ocol] = h;
            Hl[(long long)orow * NK + ocol] = l;
        }
    }
}

// attn = softmax(scores row) in place (fp32) + split bf16. D = 2048.
__global__ void __launch_bounds__(256)
attn_softmax_split_rows(float* __restrict__ X,
                        __nv_bfloat16* __restrict__ Hh, __nv_bfloat16* __restrict__ Hl)
{
    float* row = X + (size_t)blockIdx.x * NK;
    const int t = threadIdx.x;
    __shared__ float sred[8];
    float x[8];
    #pragma unroll
    for (int i = 0; i < 8; i++) x[i] = row[t + 256 * i];
    float m = -INFINITY;
    #pragma unroll
    for (int i = 0; i < 8; i++) m = fmaxf(m, x[i]);
    m = block_reduce_max(m, sred, t);
    float ex[8];
    float s = 0.f;
    #pragma unroll
    for (int i = 0; i < 8; i++) { ex[i] = expf(x[i] - m); s += ex[i]; }
    s = block_reduce_sum(s, sred, t);
    const float inv = 1.f / s;
    const size_t base = (size_t)blockIdx.x * NK + t;
    #pragma unroll
    for (int i = 0; i < 8; i++) {
        const float p = ex[i] * inv;
        row[t + 256 * i] = p;
        __nv_bfloat16 h, l;
        split1(p, h, l);
        Hh[base + 256 * i] = h;
        Hl[base + 256 * i] = l;
    }
}

// ---------------------------------------------------------------------------
// Launch (single stream, graph-capturable, no allocations)
// ---------------------------------------------------------------------------
extern "C" void kernel_launch(void* const* d_in, const int* in_sizes, int n_in,
                              void* d_out, int out_size)
{
    const float* Q  = (const float*)d_in[0];
    const float* K  = (const float*)d_in[1];
    const float* V  = (const float*)d_in[2];
    const float* Wq = (const float*)d_in[3];
    const float* bq = (const float*)d_in[4];
    const float* Wk = (const float*)d_in[5];
    const float* bk = (const float*)d_in[6];
    const float* Wv = (const float*)d_in[7];
    const float* bv = (const float*)d_in[8];

    float* out = (float*)d_out;
    const long long outElems  = (long long)BATCH * NQ * DM;
    const long long attnElems = (long long)BATCH * NQ * NK;

    cudaFuncSetAttribute((const void*)wm_gemm<0,3>, cudaFuncAttributeMaxDynamicSharedMemorySize, GEMM_SMEM);
    cudaFuncSetAttribute((const void*)wm_gemm<2,2>, cudaFuncAttributeMaxDynamicSharedMemorySize, GEMM_SMEM2);
    cudaFuncSetAttribute((const void*)proj_gemm,    cudaFuncAttributeMaxDynamicSharedMemorySize, GEMM_SMEM);

    float *Kp, *Vp, *negent, *attn_scratch;
    cudaGetSymbolAddress((void**)&Kp, g_Kp);
    cudaGetSymbolAddress((void**)&Vp, g_Vp);
    cudaGetSymbolAddress((void**)&negent, g_negent);
    cudaGetSymbolAddress((void**)&attn_scratch, g_attn);
    float* attn = ((long long)out_size >= outElems + attnElems) ? (out + outElems) : attn_scratch;

    __nv_bfloat16 *Qh, *Ql, *Kh, *Kl, *Vh, *Vl, *Wqh, *Wql, *Wkh, *Wkl, *Wvh, *Wvl;
    __nv_bfloat16 *Qph, *Qpl, *pKh, *VpTh, *VpTl, *Ath, *Atl;
    cudaGetSymbolAddress((void**)&Qh, g_Qh);   cudaGetSymbolAddress((void**)&Ql, g_Ql);
    cudaGetSymbolAddress((void**)&Kh, g_Kh);   cudaGetSymbolAddress((void**)&Kl, g_Kl);
    cudaGetSymbolAddress((void**)&Vh, g_Vh);   cudaGetSymbolAddress((void**)&Vl, g_Vl);
    cudaGetSymbolAddress((void**)&Wqh, g_Wqh); cudaGetSymbolAddress((void**)&Wql, g_Wql);
    cudaGetSymbolAddress((void**)&Wkh, g_Wkh); cudaGetSymbolAddress((void**)&Wkl, g_Wkl);
    cudaGetSymbolAddress((void**)&Wvh, g_Wvh); cudaGetSymbolAddress((void**)&Wvl, g_Wvl);
    cudaGetSymbolAddress((void**)&Qph, g_Qph); cudaGetSymbolAddress((void**)&Qpl, g_Qpl);
    cudaGetSymbolAddress((void**)&pKh, g_pKh);
    cudaGetSymbolAddress((void**)&VpTh, g_VpTh); cudaGetSymbolAddress((void**)&VpTl, g_VpTl);
    cudaGetSymbolAddress((void**)&Ath, g_Ath); cudaGetSymbolAddress((void**)&Atl, g_Atl);

    const int Mrows = BATCH * NQ;  // 8192

    // 1) input splits (one launch)
    {
        const long long bigN4 = ((long long)Mrows * DM) >> 2;
        dim3 grid((unsigned)((bigN4 + 255) / 256), 1, 6);
        split_all_kernel<<<grid, 256>>>(Q, K, V, Wq, Wk, Wv,
                                        Qh, Ql, Kh, Kl, Vh, Vl,
                                        Wqh, Wql, Wkh, Wkl, Wvh, Wvl);
    }

    // 2) merged projections; Q epilogue writes split bf16 directly
    {
        dim3 grid(DM / 128, Mrows / 128, 3);
        proj_gemm<<<grid, 256, GEMM_SMEM>>>(Qh, Ql, Kh, Kl, Vh, Vl,
                                            Wqh, Wql, Wkh, Wkl, Wvh, Wvl,
                                            bq, bk, bv, Qph, Qpl, Kp, Vp);
    }

    // 3) fused: pK softmax+entropy (hi-only split) AND Vp transpose splits
    {
        const unsigned nblocks = (unsigned)(Mrows + BATCH * 2048);
        ent_and_transpose_kernel<<<nblocks, 256>>>(Kp, pKh, negent, Vp, VpTh, VpTl);
    }

    // 4) scores = Qp . pK - negent[j], 2-term split (pK lo dropped: |pKl| <= 2^-9 p)
    {
        dim3 grid(NK / 128, NQ / 128, BATCH);
        wm_gemm<2,2><<<grid, 256, GEMM_SMEM2>>>(
            Qph, Qpl, pKh, pKh, negent, attn, NQ, NK, DM,
            (long long)NQ * DM, (long long)NK * DM, (long long)NQ * NK, (long long)NK);
    }

    // 5) attn = softmax(scores) fp32 + split bf16
    attn_softmax_split_rows<<<BATCH * NQ, 256>>>(attn, Ath, Atl);

    // 6) out = attn @ Vp (via VpT, NT form), full 3-term
    {
        dim3 grid(DM / 128, NQ / 128, BATCH);
        wm_gemm<0,3><<<grid, 256, GEMM_SMEM>>>(
            Ath, Atl, VpTh, VpTl, nullptr, out, NQ, DM, NK,
            (long long)NQ * NK, (long long)DM * NK, (long long)NQ * DM, 0);
    }
}

// round 17
// speedup vs baseline: 1.8842x; 1.1815x over previous
#include <cuda_runtime.h>
#include <cuda_bf16.h>
#include <stdint.h>
#include <math.h>

// Problem constants
#define BATCH 4
#define NQ 2048
#define NK 2048
#define DM 1024

// ---------------------------------------------------------------------------
// Scratch (device globals)
// ---------------------------------------------------------------------------
__device__ float g_Kp[BATCH * NK * DM];
__device__ float g_Vp[BATCH * NK * DM];
__device__ float g_negent[BATCH * NK];
__device__ float g_attn[BATCH * NQ * NK];

__device__ __nv_bfloat16 g_Qh[BATCH * NQ * DM],  g_Ql[BATCH * NQ * DM];
__device__ __nv_bfloat16 g_Kh[BATCH * NK * DM],  g_Kl[BATCH * NK * DM];
__device__ __nv_bfloat16 g_Vh[BATCH * NK * DM],  g_Vl[BATCH * NK * DM];
__device__ __nv_bfloat16 g_Wqh[DM * DM], g_Wql[DM * DM];
__device__ __nv_bfloat16 g_Wkh[DM * DM], g_Wkl[DM * DM];
__device__ __nv_bfloat16 g_Wvh[DM * DM], g_Wvl[DM * DM];
__device__ __nv_bfloat16 g_Qph[BATCH * NQ * DM];
__device__ __nv_bfloat16 g_pKh[BATCH * NK * DM];
__device__ __nv_bfloat16 g_VpTh[BATCH * DM * NK], g_VpTl[BATCH * DM * NK];
__device__ __nv_bfloat16 g_Ath[BATCH * NQ * NK], g_Atl[BATCH * NQ * NK];

// ---------------------------------------------------------------------------
// Common MMA helpers
// ---------------------------------------------------------------------------
#define KC 32
#define SROW 40
#define TILEE (128 * SROW)
#define GEMM_SMEM3 (2 * 4 * TILEE * 2)           // 2 stages x 4 variants (3-term)
#define GEMM_SMEM1 (2 * 2 * TILEE * 2)           // 2 stages x 2 variants (1-term)

__device__ __forceinline__ void ldsm_x4(uint32_t* r, uint32_t addr) {
    asm volatile("ldmatrix.sync.aligned.m8n8.x4.shared.b16 {%0,%1,%2,%3}, [%4];"
                 : "=r"(r[0]), "=r"(r[1]), "=r"(r[2]), "=r"(r[3]) : "r"(addr));
}
__device__ __forceinline__ void mma_bf16(float* c, const uint32_t* a, uint32_t b0, uint32_t b1) {
    asm volatile(
        "mma.sync.aligned.m16n8k16.row.col.f32.bf16.bf16.f32 "
        "{%0,%1,%2,%3}, {%4,%5,%6,%7}, {%8,%9}, {%0,%1,%2,%3};"
        : "+f"(c[0]), "+f"(c[1]), "+f"(c[2]), "+f"(c[3])
        : "r"(a[0]), "r"(a[1]), "r"(a[2]), "r"(a[3]), "r"(b0), "r"(b1));
}
__device__ __forceinline__ void split1(float v, __nv_bfloat16& h, __nv_bfloat16& l) {
    h = __float2bfloat16(v);
    l = __float2bfloat16(v - __bfloat162float(h));
}

// ---------------------------------------------------------------------------
// Mainloop body.
// NTERMS=3: acc = Ah*Bh + Al*Bh + Ah*Bl  (variants Ah, Al, Bh, Bl)
// NTERMS=2: acc = Ah*Bh + Al*Bh          (variants Ah, Al, Bh)
// NTERMS=1: acc = Ah*Bh                  (variants Ah, Bh)
// Variant order in smem: NTERMS>=2 -> [Ah, Al, Bh, (Bl)]; NTERMS==1 -> [Ah, Bh].
// ---------------------------------------------------------------------------
struct GemmCore {
    const __nv_bfloat16 *Ah, *Al, *Bh, *Bl;
    int m0, n0, K;

    template<int NTERMS>
    __device__ __forceinline__ void run(__nv_bfloat16* smem, float acc[4][4][4],
                                        int tid, int lane, int wid) const
    {
        const int NVAR = (NTERMS == 3) ? 4 : (NTERMS == 2 ? 3 : 2);
        const int m_warp = (wid >> 2) * 64;
        const int n_warp = (wid & 3) * 32;
        const int nt = K / KC;
        const int lrow = tid >> 2;
        const int lc   = (tid & 3) * 8;

        auto issue = [&](int c, int stage) {
            const int k0 = c * KC;
            __nv_bfloat16* sbase = smem + stage * NVAR * TILEE;
            const __nv_bfloat16* srcs4[4] = {Ah, Al, Bh, Bl};
            const __nv_bfloat16* srcs2[2] = {Ah, Bh};
            #pragma unroll
            for (int v = 0; v < NVAR; v++) {
                const __nv_bfloat16* src = (NTERMS == 1) ? srcs2[v] : srcs4[v];
                const bool isA = (NTERMS == 1) ? (v == 0) : (v < 2);
                const int g0 = isA ? m0 : n0;
                __nv_bfloat16* dstv = sbase + v * TILEE;
                #pragma unroll
                for (int i = 0; i < 2; i++) {
                    const int row = lrow + i * 64;
                    const void* g = src + (long long)(g0 + row) * K + k0 + lc;
                    uint32_t d = (uint32_t)__cvta_generic_to_shared(dstv + row * SROW + lc);
                    asm volatile("cp.async.cg.shared.global [%0], [%1], 16;" :: "r"(d), "l"(g));
                }
            }
            asm volatile("cp.async.commit_group;");
        };

        const int ar  = lane & 15;
        const int ac8 = (lane >> 4) & 1;
        const int br  = (lane & 7) + ((lane & 16) ? 8 : 0);
        const int bc8 = (lane >> 3) & 1;

        issue(0, 0);
        if (nt > 1) issue(1, 1);

        for (int t = 0; t < nt; t++) {
            if (t + 1 < nt) { asm volatile("cp.async.wait_group 1;"); }
            else            { asm volatile("cp.async.wait_group 0;"); }
            __syncthreads();

            const int stage = t & 1;
            const uint32_t sb = (uint32_t)__cvta_generic_to_shared(smem + stage * NVAR * TILEE);
            const uint32_t ab_h = sb;
            const uint32_t ab_l = sb + TILEE * 2;
            const uint32_t bb_h = (NTERMS == 1) ? (sb + TILEE * 2) : (sb + 2 * TILEE * 2);
            const uint32_t bb_l = sb + 3 * TILEE * 2;

            #pragma unroll
            for (int k16 = 0; k16 < 2; k16++) {
                uint32_t ah[4][4], bh[2][4];
                #pragma unroll
                for (int tm = 0; tm < 4; tm++)
                    ldsm_x4(ah[tm], ab_h + ((m_warp + tm * 16 + ar) * SROW + k16 * 16 + ac8 * 8) * 2);
                #pragma unroll
                for (int p = 0; p < 2; p++)
                    ldsm_x4(bh[p], bb_h + ((n_warp + p * 16 + br) * SROW + k16 * 16 + bc8 * 8) * 2);
                // term 0: Ah * Bh
                #pragma unroll
                for (int tm = 0; tm < 4; tm++)
                    #pragma unroll
                    for (int tn = 0; tn < 4; tn++)
                        mma_bf16(acc[tm][tn], ah[tm],
                                 bh[tn >> 1][(tn & 1) * 2], bh[tn >> 1][(tn & 1) * 2 + 1]);
                // term 1: Al * Bh
                if (NTERMS >= 2) {
                    uint32_t al[4][4];
                    #pragma unroll
                    for (int tm = 0; tm < 4; tm++)
                        ldsm_x4(al[tm], ab_l + ((m_warp + tm * 16 + ar) * SROW + k16 * 16 + ac8 * 8) * 2);
                    #pragma unroll
                    for (int tm = 0; tm < 4; tm++)
                        #pragma unroll
                        for (int tn = 0; tn < 4; tn++)
                            mma_bf16(acc[tm][tn], al[tm],
                                     bh[tn >> 1][(tn & 1) * 2], bh[tn >> 1][(tn & 1) * 2 + 1]);
                }
                // term 2: Ah * Bl
                if (NTERMS == 3) {
                    uint32_t bl[2][4];
                    #pragma unroll
                    for (int p = 0; p < 2; p++)
                        ldsm_x4(bl[p], bb_l + ((n_warp + p * 16 + br) * SROW + k16 * 16 + bc8 * 8) * 2);
                    #pragma unroll
                    for (int tm = 0; tm < 4; tm++)
                        #pragma unroll
                        for (int tn = 0; tn < 4; tn++)
                            mma_bf16(acc[tm][tn], ah[tm],
                                     bl[tn >> 1][(tn & 1) * 2], bl[tn >> 1][(tn & 1) * 2 + 1]);
                }
            }
            __syncthreads();
            if (t + 2 < nt) issue(t + 2, stage);
        }
    }
};

// ---------------------------------------------------------------------------
// Generic GEMM (scores / out), batched via z. EPI: 0 none, 2 -= vec[n].
// ---------------------------------------------------------------------------
template<int EPI, int NTERMS>
__global__ void __launch_bounds__(256, 2)
wm_gemm(const __nv_bfloat16* __restrict__ Ah_, const __nv_bfloat16* __restrict__ Al_,
        const __nv_bfloat16* __restrict__ Bh_, const __nv_bfloat16* __restrict__ Bl_,
        const float* __restrict__ vec_, float* __restrict__ C_,
        int M, int N, int K,
        long long sA, long long sB, long long sC, long long sV)
{
    extern __shared__ __align__(16) __nv_bfloat16 smem[];
    const int tid = threadIdx.x, lane = tid & 31, wid = tid >> 5;
    const long long bz = blockIdx.z;

    GemmCore core;
    core.Ah = Ah_ + bz * sA;
    core.Al = (NTERMS >= 2) ? (Al_ + bz * sA) : core.Ah;
    core.Bh = Bh_ + bz * sB;
    core.Bl = (NTERMS == 3) ? (Bl_ + bz * sB) : core.Bh;
    core.m0 = blockIdx.y * 128; core.n0 = blockIdx.x * 128; core.K = K;
    float* C = C_ + bz * sC;
    const float* vec = (EPI != 0) ? (vec_ + bz * sV) : nullptr;

    float acc[4][4][4];
    #pragma unroll
    for (int i = 0; i < 4; i++)
        #pragma unroll
        for (int j = 0; j < 4; j++)
            #pragma unroll
            for (int r = 0; r < 4; r++) acc[i][j][r] = 0.f;

    core.run<NTERMS>(smem, acc, tid, lane, wid);

    const int m_warp = (wid >> 2) * 64;
    const int n_warp = (wid & 3) * 32;
    #pragma unroll
    for (int tm = 0; tm < 4; tm++) {
        #pragma unroll
        for (int tn = 0; tn < 4; tn++) {
            const int row = core.m0 + m_warp + tm * 16 + (lane >> 2);
            const int col = core.n0 + n_warp + tn * 8 + (lane & 3) * 2;
            float2 v0 = make_float2(acc[tm][tn][0], acc[tm][tn][1]);
            float2 v1 = make_float2(acc[tm][tn][2], acc[tm][tn][3]);
            if (EPI == 2) {
                const float2 vv = *(const float2*)&vec[col];
                v0.x -= vv.x; v0.y -= vv.y; v1.x -= vv.x; v1.y -= vv.y;
            }
            *(float2*)&C[(long long)row * N + col] = v0;
            *(float2*)&C[(long long)(row + 8) * N + col] = v1;
        }
    }
}

// ---------------------------------------------------------------------------
// Merged projection GEMM: grid.z selects {Q, K, V}. P = X @ W^T + b.
// z=0 (Q): 2-term, write Qp hi bf16 only (Qpl never consumed downstream).
// z=1 (K): 2-term, write Kp fp32.
// z=2 (V): 3-term, write Vp fp32.
// ---------------------------------------------------------------------------
__global__ void __launch_bounds__(256, 2)
proj_gemm(const __nv_bfloat16* __restrict__ Qh, const __nv_bfloat16* __restrict__ Ql,
          const __nv_bfloat16* __restrict__ Kh, const __nv_bfloat16* __restrict__ Kl,
          const __nv_bfloat16* __restrict__ Vh, const __nv_bfloat16* __restrict__ Vl,
          const __nv_bfloat16* __restrict__ Wqh, const __nv_bfloat16* __restrict__ Wql,
          const __nv_bfloat16* __restrict__ Wkh, const __nv_bfloat16* __restrict__ Wkl,
          const __nv_bfloat16* __restrict__ Wvh, const __nv_bfloat16* __restrict__ Wvl,
          const float* __restrict__ bq, const float* __restrict__ bk,
          const float* __restrict__ bv,
          __nv_bfloat16* __restrict__ Qph,
          float* __restrict__ Kp, float* __restrict__ Vp)
{
    extern __shared__ __align__(16) __nv_bfloat16 smem[];
    const int tid = threadIdx.x, lane = tid & 31, wid = tid >> 5;
    const int z = blockIdx.z;

    GemmCore core;
    const float* bias;
    if (z == 0)      { core.Ah = Qh; core.Al = Ql; core.Bh = Wqh; core.Bl = Wql; bias = bq; }
    else if (z == 1) { core.Ah = Kh; core.Al = Kl; core.Bh = Wkh; core.Bl = Wkl; bias = bk; }
    else             { core.Ah = Vh; core.Al = Vl; core.Bh = Wvh; core.Bl = Wvl; bias = bv; }
    core.m0 = blockIdx.y * 128; core.n0 = blockIdx.x * 128; core.K = DM;

    float acc[4][4][4];
    #pragma unroll
    for (int i = 0; i < 4; i++)
        #pragma unroll
        for (int j = 0; j < 4; j++)
            #pragma unroll
            for (int r = 0; r < 4; r++) acc[i][j][r] = 0.f;

    if (z == 2) core.run<3>(smem, acc, tid, lane, wid);
    else        core.run<2>(smem, acc, tid, lane, wid);

    const int m_warp = (wid >> 2) * 64;
    const int n_warp = (wid & 3) * 32;
    const int N = DM;
    float* Cf = (z == 1) ? Kp : Vp;

    #pragma unroll
    for (int tm = 0; tm < 4; tm++) {
        #pragma unroll
        for (int tn = 0; tn < 4; tn++) {
            const int row = core.m0 + m_warp + tm * 16 + (lane >> 2);
            const int col = core.n0 + n_warp + tn * 8 + (lane & 3) * 2;
            const float2 bb = *(const float2*)&bias[col];
            float2 v0 = make_float2(acc[tm][tn][0] + bb.x, acc[tm][tn][1] + bb.y);
            float2 v1 = make_float2(acc[tm][tn][2] + bb.x, acc[tm][tn][3] + bb.y);
            if (z == 0) {
                *(__nv_bfloat162*)&Qph[(long long)row * N + col] =
                    __nv_bfloat162(__float2bfloat16(v0.x), __float2bfloat16(v0.y));
                *(__nv_bfloat162*)&Qph[(long long)(row + 8) * N + col] =
                    __nv_bfloat162(__float2bfloat16(v1.x), __float2bfloat16(v1.y));
            } else {
                *(float2*)&Cf[(long long)row * N + col] = v0;
                *(float2*)&Cf[(long long)(row + 8) * N + col] = v1;
            }
        }
    }
}

// ---------------------------------------------------------------------------
// Merged input splits: grid.z selects {Q, K, V, Wq, Wk, Wv}
// ---------------------------------------------------------------------------
__global__ void __launch_bounds__(256)
split_all_kernel(const float* __restrict__ Q, const float* __restrict__ K,
                 const float* __restrict__ V, const float* __restrict__ Wq,
                 const float* __restrict__ Wk, const float* __restrict__ Wv,
                 __nv_bfloat16* __restrict__ Qh, __nv_bfloat16* __restrict__ Ql,
                 __nv_bfloat16* __restrict__ Kh, __nv_bfloat16* __restrict__ Kl,
                 __nv_bfloat16* __restrict__ Vh, __nv_bfloat16* __restrict__ Vl,
                 __nv_bfloat16* __restrict__ Wqh, __nv_bfloat16* __restrict__ Wql,
                 __nv_bfloat16* __restrict__ Wkh, __nv_bfloat16* __restrict__ Wkl,
                 __nv_bfloat16* __restrict__ Wvh, __nv_bfloat16* __restrict__ Wvl)
{
    const int z = blockIdx.z;
    const long long bigN4 = ((long long)BATCH * NQ * DM) >> 2;
    const long long wN4   = ((long long)DM * DM) >> 2;
    const float* src; __nv_bfloat16 *hi, *lo; long long n4;
    switch (z) {
        case 0: src = Q;  hi = Qh;  lo = Ql;  n4 = bigN4; break;
        case 1: src = K;  hi = Kh;  lo = Kl;  n4 = bigN4; break;
        case 2: src = V;  hi = Vh;  lo = Vl;  n4 = bigN4; break;
        case 3: src = Wq; hi = Wqh; lo = Wql; n4 = wN4;   break;
        case 4: src = Wk; hi = Wkh; lo = Wkl; n4 = wN4;   break;
        default: src = Wv; hi = Wvh; lo = Wvl; n4 = wN4;  break;
    }
    const long long i = (long long)blockIdx.x * blockDim.x + threadIdx.x;
    if (i >= n4) return;
    const float4 v = ((const float4*)src)[i];
    __nv_bfloat16 h0, h1, h2, h3, l0, l1, l2, l3;
    split1(v.x, h0, l0); split1(v.y, h1, l1); split1(v.z, h2, l2); split1(v.w, h3, l3);
    ((__nv_bfloat162*)hi)[2*i]   = __nv_bfloat162(h0, h1);
    ((__nv_bfloat162*)hi)[2*i+1] = __nv_bfloat162(h2, h3);
    ((__nv_bfloat162*)lo)[2*i]   = __nv_bfloat162(l0, l1);
    ((__nv_bfloat162*)lo)[2*i+1] = __nv_bfloat162(l2, l3);
}

// ---------------------------------------------------------------------------
// Row reductions
// ---------------------------------------------------------------------------
__device__ __forceinline__ float warp_max(float v) {
    #pragma unroll
    for (int o = 16; o; o >>= 1) v = fmaxf(v, __shfl_xor_sync(0xffffffffu, v, o));
    return v;
}
__device__ __forceinline__ float warp_sum(float v) {
    #pragma unroll
    for (int o = 16; o; o >>= 1) v += __shfl_xor_sync(0xffffffffu, v, o);
    return v;
}
__device__ __forceinline__ float block_reduce_max(float v, float* sred, int t) {
    v = warp_max(v);
    if ((t & 31) == 0) sred[t >> 5] = v;
    __syncthreads();
    if (t < 32) {
        float x = (t < 8) ? sred[t] : -INFINITY;
        #pragma unroll
        for (int o = 4; o; o >>= 1) x = fmaxf(x, __shfl_xor_sync(0xffffffffu, x, o));
        if (t == 0) sred[0] = x;
    }
    __syncthreads();
    const float r = sred[0];
    __syncthreads();
    return r;
}
__device__ __forceinline__ float block_reduce_sum(float v, float* sred, int t) {
    v = warp_sum(v);
    if ((t & 31) == 0) sred[t >> 5] = v;
    __syncthreads();
    if (t < 32) {
        float x = (t < 8) ? sred[t] : 0.f;
        #pragma unroll
        for (int o = 4; o; o >>= 1) x += __shfl_xor_sync(0xffffffffu, x, o);
        if (t == 0) sred[0] = x;
    }
    __syncthreads();
    const float r = sred[0];
    __syncthreads();
    return r;
}

// ---------------------------------------------------------------------------
// Fused post-projection elementwise: one launch, two independent jobs.
//   blockIdx.x < Mrows : softmax_ent on Kp row -> pK hi split + negent
//   blockIdx.x >= Mrows: 32x32 transpose tile of Vp -> VpT splits
// ---------------------------------------------------------------------------
__global__ void __launch_bounds__(256)
ent_and_transpose_kernel(const float* __restrict__ Kp,
                         __nv_bfloat16* __restrict__ pKh,
                         float* __restrict__ negent,
                         const float* __restrict__ Vp,
                         __nv_bfloat16* __restrict__ VpTh, __nv_bfloat16* __restrict__ VpTl)
{
    const int Mrows = BATCH * NK;
    const int t = threadIdx.x;

    if ((int)blockIdx.x < Mrows) {
        const int r = blockIdx.x;
        const float* row = Kp + (size_t)r * DM;
        __shared__ float sred[8];
        float x[4];
        #pragma unroll
        for (int i = 0; i < 4; i++) x[i] = row[t + 256 * i];
        float m = fmaxf(fmaxf(x[0], x[1]), fmaxf(x[2], x[3]));
        m = block_reduce_max(m, sred, t);
        float s = 0.f;
        #pragma unroll
        for (int i = 0; i < 4; i++) s += expf(x[i] - m);
        s = block_reduce_sum(s, sred, t);
        const float lse = m + logf(s);
        const size_t base = (size_t)r * DM + t;
        float se = 0.f;
        #pragma unroll
        for (int i = 0; i < 4; i++) {
            const float lp = x[i] - lse;
            const float p = expf(lp);
            se += p * lp;
            pKh[base + 256 * i] = __float2bfloat16(p);
        }
        se = warp_sum(se);
        if ((t & 31) == 0) sred[t >> 5] = se;
        __syncthreads();
        if (t < 32) {
            float v = (t < 8) ? sred[t] : 0.f;
            #pragma unroll
            for (int o = 4; o; o >>= 1) v += __shfl_xor_sync(0xffffffffu, v, o);
            if (t == 0) negent[r] = v;
        }
    } else {
        __shared__ float tile[32][33];
        const int idx = blockIdx.x - Mrows;
        const int b   = idx >> 11;
        const int rem = idx & 2047;
        const int x0  = (rem & 31) * 32;
        const int y0  = (rem >> 5) * 32;
        const int tx = t & 31, ty = t >> 5;
        const float* S = Vp + (long long)b * NK * DM;
        #pragma unroll
        for (int j = 0; j < 32; j += 8)
            tile[ty + j][tx] = S[(long long)(y0 + ty + j) * DM + x0 + tx];
        __syncthreads();
        __nv_bfloat16* Hh = VpTh + (long long)b * DM * NK;
        __nv_bfloat16* Hl = VpTl + (long long)b * DM * NK;
        #pragma unroll
        for (int j = 0; j < 32; j += 8) {
            const float v = tile[tx][ty + j];
            const int orow = x0 + ty + j;
            const int ocol = y0 + tx;
            __nv_bfloat16 h, l;
            split1(v, h, l);
            Hh[(long long)orow * NK + ocol] = h;
            Hl[(long long)orow * NK + ocol] = l;
        }
    }
}

// attn = softmax(scores row) in place (fp32) + split bf16. D = 2048.
__global__ void __launch_bounds__(256)
attn_softmax_split_rows(float* __restrict__ X,
                        __nv_bfloat16* __restrict__ Hh, __nv_bfloat16* __restrict__ Hl)
{
    float* row = X + (size_t)blockIdx.x * NK;
    const int t = threadIdx.x;
    __shared__ float sred[8];
    float x[8];
    #pragma unroll
    for (int i = 0; i < 8; i++) x[i] = row[t + 256 * i];
    float m = -INFINITY;
    #pragma unroll
    for (int i = 0; i < 8; i++) m = fmaxf(m, x[i]);
    m = block_reduce_max(m, sred, t);
    float ex[8];
    float s = 0.f;
    #pragma unroll
    for (int i = 0; i < 8; i++) { ex[i] = expf(x[i] - m); s += ex[i]; }
    s = block_reduce_sum(s, sred, t);
    const float inv = 1.f / s;
    const size_t base = (size_t)blockIdx.x * NK + t;
    #pragma unroll
    for (int i = 0; i < 8; i++) {
        const float p = ex[i] * inv;
        row[t + 256 * i] = p;
        __nv_bfloat16 h, l;
        split1(p, h, l);
        Hh[base + 256 * i] = h;
        Hl[base + 256 * i] = l;
    }
}

// ---------------------------------------------------------------------------
// Launch (single stream, graph-capturable, no allocations)
// ---------------------------------------------------------------------------
extern "C" void kernel_launch(void* const* d_in, const int* in_sizes, int n_in,
                              void* d_out, int out_size)
{
    const float* Q  = (const float*)d_in[0];
    const float* K  = (const float*)d_in[1];
    const float* V  = (const float*)d_in[2];
    const float* Wq = (const float*)d_in[3];
    const float* bq = (const float*)d_in[4];
    const float* Wk = (const float*)d_in[5];
    const float* bk = (const float*)d_in[6];
    const float* Wv = (const float*)d_in[7];
    const float* bv = (const float*)d_in[8];

    float* out = (float*)d_out;
    const long long outElems  = (long long)BATCH * NQ * DM;
    const long long attnElems = (long long)BATCH * NQ * NK;

    cudaFuncSetAttribute((const void*)wm_gemm<0,3>, cudaFuncAttributeMaxDynamicSharedMemorySize, GEMM_SMEM3);
    cudaFuncSetAttribute((const void*)wm_gemm<2,1>, cudaFuncAttributeMaxDynamicSharedMemorySize, GEMM_SMEM1);
    cudaFuncSetAttribute((const void*)proj_gemm,    cudaFuncAttributeMaxDynamicSharedMemorySize, GEMM_SMEM3);

    float *Kp, *Vp, *negent, *attn_scratch;
    cudaGetSymbolAddress((void**)&Kp, g_Kp);
    cudaGetSymbolAddress((void**)&Vp, g_Vp);
    cudaGetSymbolAddress((void**)&negent, g_negent);
    cudaGetSymbolAddress((void**)&attn_scratch, g_attn);
    float* attn = ((long long)out_size >= outElems + attnElems) ? (out + outElems) : attn_scratch;

    __nv_bfloat16 *Qh, *Ql, *Kh, *Kl, *Vh, *Vl, *Wqh, *Wql, *Wkh, *Wkl, *Wvh, *Wvl;
    __nv_bfloat16 *Qph, *pKh, *VpTh, *VpTl, *Ath, *Atl;
    cudaGetSymbolAddress((void**)&Qh, g_Qh);   cudaGetSymbolAddress((void**)&Ql, g_Ql);
    cudaGetSymbolAddress((void**)&Kh, g_Kh);   cudaGetSymbolAddress((void**)&Kl, g_Kl);
    cudaGetSymbolAddress((void**)&Vh, g_Vh);   cudaGetSymbolAddress((void**)&Vl, g_Vl);
    cudaGetSymbolAddress((void**)&Wqh, g_Wqh); cudaGetSymbolAddress((void**)&Wql, g_Wql);
    cudaGetSymbolAddress((void**)&Wkh, g_Wkh); cudaGetSymbolAddress((void**)&Wkl, g_Wkl);
    cudaGetSymbolAddress((void**)&Wvh, g_Wvh); cudaGetSymbolAddress((void**)&Wvl, g_Wvl);
    cudaGetSymbolAddress((void**)&Qph, g_Qph);
    cudaGetSymbolAddress((void**)&pKh, g_pKh);
    cudaGetSymbolAddress((void**)&VpTh, g_VpTh); cudaGetSymbolAddress((void**)&VpTl, g_VpTl);
    cudaGetSymbolAddress((void**)&Ath, g_Ath); cudaGetSymbolAddress((void**)&Atl, g_Atl);

    const int Mrows = BATCH * NQ;  // 8192

    // 1) input splits (one launch)
    {
        const long long bigN4 = ((long long)Mrows * DM) >> 2;
        dim3 grid((unsigned)((bigN4 + 255) / 256), 1, 6);
        split_all_kernel<<<grid, 256>>>(Q, K, V, Wq, Wk, Wv,
                                        Qh, Ql, Kh, Kl, Vh, Vl,
                                        Wqh, Wql, Wkh, Wkl, Wvh, Wvl);
    }

    // 2) merged projections: Q/K 2-term, V 3-term; Qp -> hi bf16 only
    {
        dim3 grid(DM / 128, Mrows / 128, 3);
        proj_gemm<<<grid, 256, GEMM_SMEM3>>>(Qh, Ql, Kh, Kl, Vh, Vl,
                                             Wqh, Wql, Wkh, Wkl, Wvh, Wvl,
                                             bq, bk, bv, Qph, Kp, Vp);
    }

    // 3) fused: pK softmax+entropy (hi-only) AND Vp transpose splits
    {
        const unsigned nblocks = (unsigned)(Mrows + BATCH * 2048);
        ent_and_transpose_kernel<<<nblocks, 256>>>(Kp, pKh, negent, Vp, VpTh, VpTl);
    }

    // 4) scores = Qph . pKh - negent[j], 1-term pure bf16
    //    (lo-term drops each contribute ~8e-5, calibrated by R15 measurement)
    {
        dim3 grid(NK / 128, NQ / 128, BATCH);
        wm_gemm<2,1><<<grid, 256, GEMM_SMEM1>>>(
            Qph, Qph, pKh, pKh, negent, attn, NQ, NK, DM,
            (long long)NQ * DM, (long long)NK * DM, (long long)NQ * NK, (long long)NK);
    }

    // 5) attn = softmax(scores) fp32 + split bf16
    attn_softmax_split_rows<<<BATCH * NQ, 256>>>(attn, Ath, Atl);

    // 6) out = attn @ Vp (via VpT, NT form), full 3-term
    {
        dim3 grid(DM / 128, NQ / 128, BATCH);
        wm_gemm<0,3><<<grid, 256, GEMM_SMEM3>>>(
            Ath, Atl, VpTh, VpTl, nullptr, out, NQ, DM, NK,
            (long long)NQ * NK, (long long)DM * NK, (long long)NQ * DM, 0);
    }
}